// round 12
// baseline (speedup 1.0000x reference)
#include <cuda_runtime.h>
#include <math.h>

#define LSEQ 200
#define HSTR 68      // histL row stride (floats)
#define MP_STR 68    // Mp row stride (uint2)
#define W1P_STR 36   // W1p row stride (uint2)
#define NTHR 416     // 13 warps
#define SAMPLES 4

__device__ __align__(16) unsigned int g_B3p[32 * 64 * 2];       // W_t - W_d packed tf32 pairs
__device__ __align__(16) unsigned int g_W1p[32 * W1P_STR * 2];  // aW1 packed tf32 pairs

typedef unsigned long long u64t;
typedef unsigned int u32t;

__device__ __forceinline__ u64t dup2(float x) {
    u64t r; asm("mov.b64 %0, {%1, %1};" : "=l"(r) : "f"(x)); return r;
}
__device__ __forceinline__ void fma2(u64t& d, u64t a, u64t b) {
    asm("fma.rn.f32x2 %0, %1, %2, %0;" : "+l"(d) : "l"(a), "l"(b));
}
__device__ __forceinline__ void unpack2(u64t v, float& a, float& b) {
    asm("mov.b64 {%0, %1}, %2;" : "=f"(a), "=f"(b) : "l"(v));
}
__device__ __forceinline__ u32t f2tf32(float f) {
    u32t u; asm("cvt.rna.tf32.f32 %0, %1;" : "=r"(u) : "f"(f)); return u;
}
__device__ __forceinline__ void mma_tf32(float& d0, float& d1, float& d2, float& d3,
                                         u32t a0, u32t a1, u32t a2, u32t a3,
                                         u32t b0, u32t b1) {
    asm volatile(
        "mma.sync.aligned.m16n8k8.row.col.f32.tf32.tf32.f32 "
        "{%0,%1,%2,%3},{%4,%5,%6,%7},{%8,%9},{%0,%1,%2,%3};"
        : "+f"(d0), "+f"(d1), "+f"(d2), "+f"(d3)
        : "r"(a0), "r"(a1), "r"(a2), "r"(a3), "r"(b0), "r"(b1));
}

// ---- precompute static tf32-packed weights ----
__global__ void precompute_kernel(const float* __restrict__ aW0,
                                  const float* __restrict__ aW1)
{
    int idx = blockIdx.x * blockDim.x + threadIdx.x;
    int stride = gridDim.x * blockDim.x;
    for (int p = idx; p < 4096; p += stride) {
        int k = p >> 6, j = p & 63;
        float b3 = aW0[(64 + k) * 64 + j] - aW0[(192 + k) * 64 + j];
        int kt = k >> 3, r = k & 7, tg = r & 3, half = r >> 2;
        g_B3p[(((kt * 4 + tg) * 64) + j) * 2 + half] = f2tf32(b3);
    }
    for (int p = idx; p < 2048; p += stride) {
        int k = p >> 5, j = p & 31;
        int kt = k >> 3, r = k & 7, tg = r & 3, half = r >> 2;
        g_W1p[(((kt * 4 + tg) * W1P_STR) + j) * 2 + half] = f2tf32(aW1[p]);
    }
}

struct __align__(16) SmemA {
    float histL[208 * HSTR];     // 56576 B
    uint2 Mp[32 * MP_STR];       // 17408 B (per-sample M, tf32 packed)
    uint2 W1p[32 * W1P_STR];     // 9216 B
    float xsT[244 * SAMPLES];    // 3904 B  x features, transposed [i][s]
    float h0T[256 * SAMPLES];    // 4096 B
    float h1s[SAMPLES * 128];    // 2048 B
    float t[64];
    float ab0s[64];
    float cbias[64];
    float ab1s[32];
    float aW2s[32];
    float scores[208];
    float red[16];
    float poolbuf[26 * 64];      // 6656 B
};

__global__ __launch_bounds__(NTHR, 2) void attn_kernel(
    const int* __restrict__ user_id, const int* __restrict__ item_id,
    const int* __restrict__ item_category, const int* __restrict__ item_dur_bkt,
    const float* __restrict__ user_dense, const float* __restrict__ item_dense,
    const int* __restrict__ history_seq,
    const float* __restrict__ user_W, const float* __restrict__ item_W,
    const float* __restrict__ cat_W, const float* __restrict__ dur_W,
    const float* __restrict__ hist_W,
    const float* __restrict__ aW0, const float* __restrict__ ab0,
    const float* __restrict__ ab1, const float* __restrict__ aW2,
    const float* __restrict__ ab2,
    const float* __restrict__ mW0, const float* __restrict__ mb0,
    const float* __restrict__ mW1, const float* __restrict__ mb1,
    const float* __restrict__ mW2, const float* __restrict__ mb2,
    float* __restrict__ out, int B)
{
    extern __shared__ char smem_raw[];
    SmemA& S = *reinterpret_cast<SmemA*>(smem_raw);
    float* Mpf = (float*)S.Mp;
    const int tid = threadIdx.x;
    const int lane = tid & 31;
    const int w = tid >> 5;            // 0..12

    const int gid = lane >> 2;   // 0..7
    const int tig = lane & 3;    // 0..3
    const bool odd = tig & 1;
    const int src0 = gid * 4 + (tig >> 1);
    const int src2 = src0 + 2;
    const float ab2v = ab2[0];

    // ---- once-per-block: stage W1p, vectors, zero pads ----
    for (int i = tid; i < 576; i += NTHR)
        ((uint4*)S.W1p)[i] = ((const uint4*)g_W1p)[i];
    if (tid < 64) S.ab0s[tid] = ab0[tid];
    else if (tid < 96) { S.aW2s[tid - 64] = aW2[tid - 64]; S.ab1s[tid - 64] = ab1[tid - 64]; }
    for (int p = tid; p < 8 * 64; p += NTHR)
        S.histL[(LSEQ + (p >> 6)) * HSTR + (p & 63)] = 0.f;

    for (int s = 0; s < SAMPLES; s++) {
        int b = blockIdx.x * SAMPLES + s;
        if (b >= B) b = B - 1;

        // ---- per-sample: t + fully-parallel gather ----
        if (tid < 64) S.t[tid] = item_W[item_id[b] * 64 + tid];
        {
            int c8 = tid & 7, lb = tid >> 3;   // lb: 0..51
            const int* hs = &history_seq[b * LSEQ];
            int r0 = hs[lb];
            int r1 = hs[lb + 52];
            int r2 = hs[lb + 104];
            bool has3 = (lb + 156) < LSEQ;
            int r3 = has3 ? hs[lb + 156] : 0;
            const float4* p0 = (const float4*)&hist_W[r0 * 64] + c8 * 2;
            const float4* p1 = (const float4*)&hist_W[r1 * 64] + c8 * 2;
            const float4* p2 = (const float4*)&hist_W[r2 * 64] + c8 * 2;
            const float4* p3 = (const float4*)&hist_W[r3 * 64] + c8 * 2;
            float4 a0 = p0[0], a1 = p0[1];
            float4 b0 = p1[0], b1 = p1[1];
            float4 c0 = p2[0], c1 = p2[1];
            float4 d0 = p3[0], d1 = p3[1];
            float* dst0 = &S.histL[lb * HSTR + c8 * 8];
            *(float4*)dst0 = a0; *(float4*)(dst0 + 4) = a1;
            float* dst1 = &S.histL[(lb + 52) * HSTR + c8 * 8];
            *(float4*)dst1 = b0; *(float4*)(dst1 + 4) = b1;
            float* dst2 = &S.histL[(lb + 104) * HSTR + c8 * 8];
            *(float4*)dst2 = c0; *(float4*)(dst2 + 4) = c1;
            if (has3) {
                float* dst3 = &S.histL[(lb + 156) * HSTR + c8 * 8];
                *(float4*)dst3 = d0; *(float4*)(dst3 + 4) = d1;
            }
        }
        __syncthreads();

        // ---- Mp build + cbias via MMA ----
        for (int g4 = tid; g4 < 1024; g4 += NTHR) {
            int k = g4 >> 4, j4 = (g4 & 15) << 2;
            float tk = S.t[k];
            float4 a0v  = *(const float4*)&aW0[k * 64 + j4];
            float4 a192 = *(const float4*)&aW0[(192 + k) * 64 + j4];
            float4 a128 = *(const float4*)&aW0[(128 + k) * 64 + j4];
            int kt = k >> 3, r = k & 7, tg = r & 3, half = r >> 2;
            float* dst = &Mpf[((kt * 4 + tg) * MP_STR) * 2 + half];
            dst[(j4 + 0) * 2] = __uint_as_float(f2tf32(a0v.x + a192.x + tk * a128.x));
            dst[(j4 + 1) * 2] = __uint_as_float(f2tf32(a0v.y + a192.y + tk * a128.y));
            dst[(j4 + 2) * 2] = __uint_as_float(f2tf32(a0v.z + a192.z + tk * a128.z));
            dst[(j4 + 3) * 2] = __uint_as_float(f2tf32(a0v.w + a192.w + tk * a128.w));
        }
        if (w < 8) {
            float d0 = 0.f, d1 = 0.f, d2 = 0.f, d3 = 0.f;
            #pragma unroll
            for (int kt = 0; kt < 8; kt++) {
                u32t ua0 = f2tf32(S.t[kt * 8 + tig]);
                u32t ua2 = f2tf32(S.t[kt * 8 + tig + 4]);
                uint2 bb = ((const uint2*)g_B3p)[(kt * 4 + tig) * 64 + w * 8 + gid];
                mma_tf32(d0, d1, d2, d3, ua0, ua0, ua2, ua2, bb.x, bb.y);
            }
            if (gid == 0) {
                S.cbias[w * 8 + 2 * tig]     = S.ab0s[w * 8 + 2 * tig] + d0;
                S.cbias[w * 8 + 2 * tig + 1] = S.ab0s[w * 8 + 2 * tig + 1] + d1;
            }
        }
        __syncthreads();

        // ---- mainloop: warp w owns l-tile w ----
        {
            const int l0 = w * 16;

            float C1[8][4] = {};
            #pragma unroll
            for (int kt = 0; kt < 8; kt++) {
                const float* ap = &S.histL[(l0 + gid) * HSTR + kt * 8 + tig];
                u32t ua0 = f2tf32(ap[0]);
                u32t ua1 = f2tf32(ap[8 * HSTR]);
                u32t ua2 = f2tf32(ap[4]);
                u32t ua3 = f2tf32(ap[8 * HSTR + 4]);
                const uint2* bp = &S.Mp[(kt * 4 + tig) * MP_STR + gid];
                #pragma unroll
                for (int jt = 0; jt < 8; jt++) {
                    uint2 bb = bp[jt * 8];
                    mma_tf32(C1[jt][0], C1[jt][1], C1[jt][2], C1[jt][3],
                             ua0, ua1, ua2, ua3, bb.x, bb.y);
                }
            }
            #pragma unroll
            for (int jt = 0; jt < 8; jt++) {
                float cb0 = S.cbias[jt * 8 + 2 * tig], cb1 = S.cbias[jt * 8 + 2 * tig + 1];
                C1[jt][0] = fmaxf(C1[jt][0] + cb0, 0.f);
                C1[jt][1] = fmaxf(C1[jt][1] + cb1, 0.f);
                C1[jt][2] = fmaxf(C1[jt][2] + cb0, 0.f);
                C1[jt][3] = fmaxf(C1[jt][3] + cb1, 0.f);
            }

            float C2[4][4] = {};
            #pragma unroll
            for (int kt = 0; kt < 8; kt++) {
                float v00 = __shfl_sync(0xffffffffu, C1[kt][0], src0);
                float v01 = __shfl_sync(0xffffffffu, C1[kt][1], src0);
                float v10 = __shfl_sync(0xffffffffu, C1[kt][2], src0);
                float v11 = __shfl_sync(0xffffffffu, C1[kt][3], src0);
                float v20 = __shfl_sync(0xffffffffu, C1[kt][0], src2);
                float v21 = __shfl_sync(0xffffffffu, C1[kt][1], src2);
                float v30 = __shfl_sync(0xffffffffu, C1[kt][2], src2);
                float v31 = __shfl_sync(0xffffffffu, C1[kt][3], src2);
                u32t ua0 = f2tf32(odd ? v01 : v00);
                u32t ua1 = f2tf32(odd ? v11 : v10);
                u32t ua2 = f2tf32(odd ? v21 : v20);
                u32t ua3 = f2tf32(odd ? v31 : v30);
                const uint2* bp = &S.W1p[(kt * 4 + tig) * W1P_STR + gid];
                #pragma unroll
                for (int jt = 0; jt < 4; jt++) {
                    uint2 bb = bp[jt * 8];
                    mma_tf32(C2[jt][0], C2[jt][1], C2[jt][2], C2[jt][3],
                             ua0, ua1, ua2, ua3, bb.x, bb.y);
                }
            }
            float sr = 0.f, sr8 = 0.f;
            #pragma unroll
            for (int jt = 0; jt < 4; jt++) {
                int j = jt * 8 + 2 * tig;
                float b0v = S.ab1s[j], b1v = S.ab1s[j + 1];
                float w0v = S.aW2s[j], w1v = S.aW2s[j + 1];
                sr  += fmaxf(C2[jt][0] + b0v, 0.f) * w0v + fmaxf(C2[jt][1] + b1v, 0.f) * w1v;
                sr8 += fmaxf(C2[jt][2] + b0v, 0.f) * w0v + fmaxf(C2[jt][3] + b1v, 0.f) * w1v;
            }
            sr  += __shfl_xor_sync(0xffffffffu, sr, 1);
            sr  += __shfl_xor_sync(0xffffffffu, sr, 2);
            sr8 += __shfl_xor_sync(0xffffffffu, sr8, 1);
            sr8 += __shfl_xor_sync(0xffffffffu, sr8, 2);
            if (tig == 0) {
                S.scores[l0 + gid]     = sr + ab2v;
                S.scores[l0 + gid + 8] = sr8 + ab2v;
            }
        }
        __syncthreads();

        // ---- mask + softmax ----
        {
            float sv = -3.402823466e38f;
            if (tid < LSEQ) {
                sv = S.scores[tid];
                if (history_seq[b * LSEQ + tid] == 0) sv = -1.0e9f;
            }
            float v = sv;
            #pragma unroll
            for (int o = 16; o; o >>= 1) v = fmaxf(v, __shfl_xor_sync(0xffffffffu, v, o));
            if (lane == 0) S.red[w] = v;
            __syncthreads();
            if (tid < 32) {
                float r = (tid < 13) ? S.red[tid] : -3.402823466e38f;
                #pragma unroll
                for (int o = 8; o; o >>= 1) r = fmaxf(r, __shfl_xor_sync(0xffffffffu, r, o));
                if (tid == 0) S.red[13] = r;
            }
            __syncthreads();
            float mx = S.red[13];
            float e = (tid < LSEQ) ? expf(sv - mx) : 0.f;
            float v2 = e;
            #pragma unroll
            for (int o = 16; o; o >>= 1) v2 += __shfl_xor_sync(0xffffffffu, v2, o);
            if (lane == 0) S.red[w] = v2;
            __syncthreads();
            if (tid < 32) {
                float r = (tid < 13) ? S.red[tid] : 0.f;
                #pragma unroll
                for (int o = 8; o; o >>= 1) r += __shfl_xor_sync(0xffffffffu, r, o);
                if (tid == 0) S.red[13] = r;
            }
            __syncthreads();
            float inv = 1.f / S.red[13];
            if (tid < LSEQ) S.scores[tid] = e * inv;
        }
        __syncthreads();

        // ---- pooling (fp32, f32x2) ----
        {
            int kq = tid & 15, lg = tid >> 4;   // lg: 0..25
            int k4 = kq * 4;
            u64t a01 = 0ull, a23 = 0ull;
            for (int l = lg; l < LSEQ; l += 26) {
                u64t sd = dup2(S.scores[l]);
                ulonglong2 h = *(const ulonglong2*)&S.histL[l * HSTR + k4];
                fma2(a01, h.x, sd);
                fma2(a23, h.y, sd);
            }
            float p0, p1, p2, p3;
            unpack2(a01, p0, p1);
            unpack2(a23, p2, p3);
            S.poolbuf[lg * 64 + k4 + 0] = p0;
            S.poolbuf[lg * 64 + k4 + 1] = p1;
            S.poolbuf[lg * 64 + k4 + 2] = p2;
            S.poolbuf[lg * 64 + k4 + 3] = p3;
        }
        __syncthreads();
        if (tid < 64) {
            float p = 0.f;
            #pragma unroll
            for (int g = 0; g < 26; g++) p += S.poolbuf[g * 64 + tid];
            S.xsT[(180 + tid) * SAMPLES + s] = p;
        }
        // ---- assemble x column s (transposed for f32x2 MLP) ----
        if (tid < 64) {
            S.xsT[tid * SAMPLES + s] = user_W[user_id[b] * 64 + tid];
        } else if (tid < 128) {
            S.xsT[tid * SAMPLES + s] = S.t[tid - 64];
        } else if (tid < 144) {
            S.xsT[tid * SAMPLES + s] = cat_W[item_category[b] * 16 + (tid - 128)];
        } else if (tid < 152) {
            S.xsT[tid * SAMPLES + s] = dur_W[item_dur_bkt[b] * 8 + (tid - 144)];
        } else if (tid < 177) {
            S.xsT[tid * SAMPLES + s] = user_dense[b * 25 + (tid - 152)];
        } else if (tid < 180) {
            S.xsT[tid * SAMPLES + s] = item_dense[b * 3 + (tid - 177)];
        }
        __syncthreads();   // histL/t/Mp/scores reuse + xsT visibility
    }

    // ================= fused MLP for the block's 4 samples =================
    // layer 0: 244 -> 256 (threads 0..255 = output cols; x reads are broadcasts)
    if (tid < 256) {
        u64t acc0 = dup2(mb0[tid]), acc1 = acc0;
        #pragma unroll 1
        for (int i = 0; i < 240; i += 8) {
            float wv[8];
            #pragma unroll
            for (int u = 0; u < 8; u++) wv[u] = mW0[(i + u) * 256 + tid];
            #pragma unroll
            for (int u = 0; u < 8; u++) {
                u64t wd = dup2(wv[u]);
                ulonglong2 x01 = *(const ulonglong2*)&S.xsT[(i + u) * SAMPLES];
                fma2(acc0, x01.x, wd);
                fma2(acc1, x01.y, wd);
            }
        }
        #pragma unroll
        for (int i = 240; i < 244; i++) {
            u64t wd = dup2(mW0[i * 256 + tid]);
            ulonglong2 x01 = *(const ulonglong2*)&S.xsT[i * SAMPLES];
            fma2(acc0, x01.x, wd);
            fma2(acc1, x01.y, wd);
        }
        float a, c;
        unpack2(acc0, a, c);
        S.h0T[tid * SAMPLES + 0] = fmaxf(a, 0.f);
        S.h0T[tid * SAMPLES + 1] = fmaxf(c, 0.f);
        unpack2(acc1, a, c);
        S.h0T[tid * SAMPLES + 2] = fmaxf(a, 0.f);
        S.h0T[tid * SAMPLES + 3] = fmaxf(c, 0.f);
    }
    __syncthreads();

    // layer 1: 256 -> 128 (threads 0..255; j = tid&127, half h handles samples {2h, 2h+1})
    if (tid < 256) {
        int j = tid & 127, h = tid >> 7;
        u64t acc = dup2(mb1[j]);
        #pragma unroll 1
        for (int i = 0; i < 256; i += 8) {
            float wv[8];
            #pragma unroll
            for (int u = 0; u < 8; u++) wv[u] = mW1[(i + u) * 128 + j];
            #pragma unroll
            for (int u = 0; u < 8; u++) {
                u64t wd = dup2(wv[u]);
                u64t av = *(const u64t*)&S.h0T[(i + u) * SAMPLES + h * 2];
                fma2(acc, av, wd);
            }
        }
        float a, c;
        unpack2(acc, a, c);
        S.h1s[(h * 2 + 0) * 128 + j] = fmaxf(a, 0.f);
        S.h1s[(h * 2 + 1) * 128 + j] = fmaxf(c, 0.f);
    }
    __syncthreads();

    // layer 2: 128 -> 1, sigmoid; warps 0..3, one sample each
    if (w < SAMPLES) {
        int b = blockIdx.x * SAMPLES + w;
        float m0 = mW2[lane], m1 = mW2[lane + 32], m2 = mW2[lane + 64], m3 = mW2[lane + 96];
        const float* hp = &S.h1s[w * 128];
        float v = hp[lane] * m0 + hp[lane + 32] * m1 + hp[lane + 64] * m2 + hp[lane + 96] * m3;
        #pragma unroll
        for (int o = 16; o; o >>= 1) v += __shfl_xor_sync(0xffffffffu, v, o);
        if (lane == 0 && b < B) {
            float logit = v + mb2[0];
            out[b] = 1.f / (1.f + expf(-logit));
        }
    }
}

extern "C" void kernel_launch(void* const* d_in, const int* in_sizes, int n_in,
                              void* d_out, int out_size)
{
    const int*   user_id       = (const int*)d_in[0];
    const int*   item_id       = (const int*)d_in[1];
    const int*   item_category = (const int*)d_in[2];
    const int*   item_dur_bkt  = (const int*)d_in[3];
    const float* user_dense    = (const float*)d_in[4];
    const float* item_dense    = (const float*)d_in[5];
    const int*   history_seq   = (const int*)d_in[6];
    const float* user_W        = (const float*)d_in[7];
    const float* item_W        = (const float*)d_in[8];
    const float* cat_W         = (const float*)d_in[9];
    const float* dur_W         = (const float*)d_in[10];
    const float* hist_W        = (const float*)d_in[11];
    const float* aW0 = (const float*)d_in[12];
    const float* ab0 = (const float*)d_in[13];
    const float* aW1 = (const float*)d_in[14];
    const float* ab1 = (const float*)d_in[15];
    const float* aW2 = (const float*)d_in[16];
    const float* ab2 = (const float*)d_in[17];
    const float* mW0 = (const float*)d_in[18];
    const float* mb0 = (const float*)d_in[19];
    const float* mW1 = (const float*)d_in[20];
    const float* mb1 = (const float*)d_in[21];
    const float* mW2 = (const float*)d_in[22];
    const float* mb2 = (const float*)d_in[23];

    const int B = in_sizes[0];
    float* out = (float*)d_out;

    precompute_kernel<<<16, 256>>>(aW0, aW1);

    cudaFuncSetAttribute(attn_kernel, cudaFuncAttributeMaxDynamicSharedMemorySize,
                         (int)sizeof(SmemA));

    attn_kernel<<<(B + SAMPLES - 1) / SAMPLES, NTHR, sizeof(SmemA)>>>(
        user_id, item_id, item_category, item_dur_bkt,
        user_dense, item_dense, history_seq,
        user_W, item_W, cat_W, dur_W, hist_W,
        aW0, ab0, ab1, aW2, ab2,
        mW0, mb0, mW1, mb1, mW2, mb2,
        out, B);
}

// round 13
// speedup vs baseline: 1.0533x; 1.0533x over previous
#include <cuda_runtime.h>
#include <math.h>

#define LSEQ 200
#define HSTR 68      // histL row stride (floats)
#define MP_STR 68    // B1p/B2p row stride (uint2)
#define W1P_STR 36   // W1p row stride (uint2)
#define NTHR 416     // 13 warps
#define SAMPLES 4
#define B_MAX 4096

__device__ float g_xbuf[B_MAX * 244];
__device__ __align__(16) unsigned int g_B1p[32 * MP_STR * 2];   // W_h + W_d packed tf32 pairs
__device__ __align__(16) unsigned int g_B2p[32 * MP_STR * 2];   // W_p packed tf32 pairs
__device__ __align__(16) unsigned int g_B3p[32 * 64 * 2];       // W_t - W_d packed tf32 pairs
__device__ __align__(16) unsigned int g_W1p[32 * W1P_STR * 2];  // aW1 packed tf32 pairs

typedef unsigned long long u64t;
typedef unsigned int u32t;

__device__ __forceinline__ u64t dup2(float x) {
    u64t r; asm("mov.b64 %0, {%1, %1};" : "=l"(r) : "f"(x)); return r;
}
__device__ __forceinline__ void fma2(u64t& d, u64t a, u64t b) {
    asm("fma.rn.f32x2 %0, %1, %2, %0;" : "+l"(d) : "l"(a), "l"(b));
}
__device__ __forceinline__ void unpack2(u64t v, float& a, float& b) {
    asm("mov.b64 {%0, %1}, %2;" : "=f"(a), "=f"(b) : "l"(v));
}
__device__ __forceinline__ u32t f2tf32(float f) {
    u32t u; asm("cvt.rna.tf32.f32 %0, %1;" : "=r"(u) : "f"(f)); return u;
}
__device__ __forceinline__ void mma_tf32(float& d0, float& d1, float& d2, float& d3,
                                         u32t a0, u32t a1, u32t a2, u32t a3,
                                         u32t b0, u32t b1) {
    asm volatile(
        "mma.sync.aligned.m16n8k8.row.col.f32.tf32.tf32.f32 "
        "{%0,%1,%2,%3},{%4,%5,%6,%7},{%8,%9},{%0,%1,%2,%3};"
        : "+f"(d0), "+f"(d1), "+f"(d2), "+f"(d3)
        : "r"(a0), "r"(a1), "r"(a2), "r"(a3), "r"(b0), "r"(b1));
}

// ---- precompute static tf32-packed weights ----
__global__ void precompute_kernel(const float* __restrict__ aW0,
                                  const float* __restrict__ aW1)
{
    int idx = blockIdx.x * blockDim.x + threadIdx.x;
    int stride = gridDim.x * blockDim.x;
    for (int p = idx; p < 4096; p += stride) {
        int k = p >> 6, j = p & 63;
        float b1 = aW0[k * 64 + j] + aW0[(192 + k) * 64 + j];
        float b2 = aW0[(128 + k) * 64 + j];
        float b3 = aW0[(64 + k) * 64 + j] - aW0[(192 + k) * 64 + j];
        int kt = k >> 3, r = k & 7, tg = r & 3, half = r >> 2;
        g_B1p[(((kt * 4 + tg) * MP_STR) + j) * 2 + half] = f2tf32(b1);
        g_B2p[(((kt * 4 + tg) * MP_STR) + j) * 2 + half] = f2tf32(b2);
        g_B3p[(((kt * 4 + tg) * 64) + j) * 2 + half]     = f2tf32(b3);
    }
    for (int p = idx; p < 2048; p += stride) {
        int k = p >> 5, j = p & 31;
        int kt = k >> 3, r = k & 7, tg = r & 3, half = r >> 2;
        g_W1p[(((kt * 4 + tg) * W1P_STR) + j) * 2 + half] = f2tf32(aW1[p]);
    }
}

struct __align__(16) SmemA {
    float histL[208 * HSTR];     // 56576 B
    uint2 B1p[32 * MP_STR];      // 17408 B
    uint2 B2p[32 * MP_STR];      // 17408 B
    uint2 W1p[32 * W1P_STR];     // 9216 B
    float t[64];
    float ab0s[64];
    float cbias[64];
    float ab1s[32];
    float aW2s[32];
    float scores[208];
    float red[16];
    float poolbuf[26 * 64];      // 6656 B
};

__global__ __launch_bounds__(NTHR, 2) void attn_kernel(
    const int* __restrict__ user_id, const int* __restrict__ item_id,
    const int* __restrict__ item_category, const int* __restrict__ item_dur_bkt,
    const float* __restrict__ user_dense, const float* __restrict__ item_dense,
    const int* __restrict__ history_seq,
    const float* __restrict__ user_W, const float* __restrict__ item_W,
    const float* __restrict__ cat_W, const float* __restrict__ dur_W,
    const float* __restrict__ hist_W,
    const float* __restrict__ ab0, const float* __restrict__ ab1,
    const float* __restrict__ aW2, const float* __restrict__ ab2, int B)
{
    extern __shared__ char smem_raw[];
    SmemA& S = *reinterpret_cast<SmemA*>(smem_raw);
    const int tid = threadIdx.x;
    const int lane = tid & 31;
    const int w = tid >> 5;            // 0..12

    const int gid = lane >> 2;   // 0..7
    const int tig = lane & 3;    // 0..3
    const bool odd = tig & 1;
    const int src0 = gid * 4 + (tig >> 1);
    const int src2 = src0 + 2;
    const float ab2v = ab2[0];

    // ---- once-per-block: stage B1p/B2p/W1p, vectors, zero pads ----
    for (int i = tid; i < 1088; i += NTHR)
        ((uint4*)S.B1p)[i] = ((const uint4*)g_B1p)[i];
    for (int i = tid; i < 1088; i += NTHR)
        ((uint4*)S.B2p)[i] = ((const uint4*)g_B2p)[i];
    for (int i = tid; i < 576; i += NTHR)
        ((uint4*)S.W1p)[i] = ((const uint4*)g_W1p)[i];
    if (tid < 64) S.ab0s[tid] = ab0[tid];
    else if (tid < 96) { S.aW2s[tid - 64] = aW2[tid - 64]; S.ab1s[tid - 64] = ab1[tid - 64]; }
    for (int p = tid; p < 8 * 64; p += NTHR)
        S.histL[(LSEQ + (p >> 6)) * HSTR + (p & 63)] = 0.f;

    for (int s = 0; s < SAMPLES; s++) {
        int b = blockIdx.x * SAMPLES + s;
        if (b >= B) b = B - 1;

        // ---- per-sample: t + fully-parallel gather ----
        if (tid < 64) S.t[tid] = item_W[item_id[b] * 64 + tid];
        {
            int c8 = tid & 7, lb = tid >> 3;   // lb: 0..51
            const int* hs = &history_seq[b * LSEQ];
            int r0 = hs[lb];
            int r1 = hs[lb + 52];
            int r2 = hs[lb + 104];
            bool has3 = (lb + 156) < LSEQ;
            int r3 = has3 ? hs[lb + 156] : 0;
            const float4* p0 = (const float4*)&hist_W[r0 * 64] + c8 * 2;
            const float4* p1 = (const float4*)&hist_W[r1 * 64] + c8 * 2;
            const float4* p2 = (const float4*)&hist_W[r2 * 64] + c8 * 2;
            const float4* p3 = (const float4*)&hist_W[r3 * 64] + c8 * 2;
            float4 a0 = p0[0], a1 = p0[1];
            float4 b0 = p1[0], b1 = p1[1];
            float4 c0 = p2[0], c1 = p2[1];
            float4 d0 = p3[0], d1 = p3[1];
            float* dst0 = &S.histL[lb * HSTR + c8 * 8];
            *(float4*)dst0 = a0; *(float4*)(dst0 + 4) = a1;
            float* dst1 = &S.histL[(lb + 52) * HSTR + c8 * 8];
            *(float4*)dst1 = b0; *(float4*)(dst1 + 4) = b1;
            float* dst2 = &S.histL[(lb + 104) * HSTR + c8 * 8];
            *(float4*)dst2 = c0; *(float4*)(dst2 + 4) = c1;
            if (has3) {
                float* dst3 = &S.histL[(lb + 156) * HSTR + c8 * 8];
                *(float4*)dst3 = d0; *(float4*)(dst3 + 4) = d1;
            }
        }
        __syncthreads();

        // ---- cbias via MMA (warps 0..7) ----
        if (w < 8) {
            float d0 = 0.f, d1 = 0.f, d2 = 0.f, d3 = 0.f;
            #pragma unroll
            for (int kt = 0; kt < 8; kt++) {
                u32t ua0 = f2tf32(S.t[kt * 8 + tig]);
                u32t ua2 = f2tf32(S.t[kt * 8 + tig + 4]);
                uint2 bb = ((const uint2*)g_B3p)[(kt * 4 + tig) * 64 + w * 8 + gid];
                mma_tf32(d0, d1, d2, d3, ua0, ua0, ua2, ua2, bb.x, bb.y);
            }
            if (gid == 0) {
                S.cbias[w * 8 + 2 * tig]     = S.ab0s[w * 8 + 2 * tig] + d0;
                S.cbias[w * 8 + 2 * tig + 1] = S.ab0s[w * 8 + 2 * tig + 1] + d1;
            }
        }
        __syncthreads();

        // ---- mainloop: warp w owns l-tile w; dual-B GEMM1 ----
        {
            const int l0 = w * 16;

            // GEMM1: C1 = hist@B1 + (hist*t)@B2   [16 x 64]
            float C1[8][4] = {};
            #pragma unroll
            for (int kt = 0; kt < 8; kt++) {
                const float* ap = &S.histL[(l0 + gid) * HSTR + kt * 8 + tig];
                float f0 = ap[0];
                float f1 = ap[8 * HSTR];
                float f2 = ap[4];
                float f3 = ap[8 * HSTR + 4];
                u32t ua0 = f2tf32(f0), ua1 = f2tf32(f1), ua2 = f2tf32(f2), ua3 = f2tf32(f3);
                const uint2* bp1 = &S.B1p[(kt * 4 + tig) * MP_STR + gid];
                #pragma unroll
                for (int jt = 0; jt < 8; jt++) {
                    uint2 bb = bp1[jt * 8];
                    mma_tf32(C1[jt][0], C1[jt][1], C1[jt][2], C1[jt][3],
                             ua0, ua1, ua2, ua3, bb.x, bb.y);
                }
                float t0 = S.t[kt * 8 + tig], t1 = S.t[kt * 8 + tig + 4];
                u32t ug0 = f2tf32(f0 * t0), ug1 = f2tf32(f1 * t0);
                u32t ug2 = f2tf32(f2 * t1), ug3 = f2tf32(f3 * t1);
                const uint2* bp2 = &S.B2p[(kt * 4 + tig) * MP_STR + gid];
                #pragma unroll
                for (int jt = 0; jt < 8; jt++) {
                    uint2 bb = bp2[jt * 8];
                    mma_tf32(C1[jt][0], C1[jt][1], C1[jt][2], C1[jt][3],
                             ug0, ug1, ug2, ug3, bb.x, bb.y);
                }
            }
            #pragma unroll
            for (int jt = 0; jt < 8; jt++) {
                float cb0 = S.cbias[jt * 8 + 2 * tig], cb1 = S.cbias[jt * 8 + 2 * tig + 1];
                C1[jt][0] = fmaxf(C1[jt][0] + cb0, 0.f);
                C1[jt][1] = fmaxf(C1[jt][1] + cb1, 0.f);
                C1[jt][2] = fmaxf(C1[jt][2] + cb0, 0.f);
                C1[jt][3] = fmaxf(C1[jt][3] + cb1, 0.f);
            }

            // GEMM2: C2[16 x 32] = h0[16 x 64] * aW1[64 x 32]; A frags via shfl
            float C2[4][4] = {};
            #pragma unroll
            for (int kt = 0; kt < 8; kt++) {
                float v00 = __shfl_sync(0xffffffffu, C1[kt][0], src0);
                float v01 = __shfl_sync(0xffffffffu, C1[kt][1], src0);
                float v10 = __shfl_sync(0xffffffffu, C1[kt][2], src0);
                float v11 = __shfl_sync(0xffffffffu, C1[kt][3], src0);
                float v20 = __shfl_sync(0xffffffffu, C1[kt][0], src2);
                float v21 = __shfl_sync(0xffffffffu, C1[kt][1], src2);
                float v30 = __shfl_sync(0xffffffffu, C1[kt][2], src2);
                float v31 = __shfl_sync(0xffffffffu, C1[kt][3], src2);
                u32t ua0 = f2tf32(odd ? v01 : v00);
                u32t ua1 = f2tf32(odd ? v11 : v10);
                u32t ua2 = f2tf32(odd ? v21 : v20);
                u32t ua3 = f2tf32(odd ? v31 : v30);
                const uint2* bp = &S.W1p[(kt * 4 + tig) * W1P_STR + gid];
                #pragma unroll
                for (int jt = 0; jt < 4; jt++) {
                    uint2 bb = bp[jt * 8];
                    mma_tf32(C2[jt][0], C2[jt][1], C2[jt][2], C2[jt][3],
                             ua0, ua1, ua2, ua3, bb.x, bb.y);
                }
            }
            float sr = 0.f, sr8 = 0.f;
            #pragma unroll
            for (int jt = 0; jt < 4; jt++) {
                int j = jt * 8 + 2 * tig;
                float b0v = S.ab1s[j], b1v = S.ab1s[j + 1];
                float w0v = S.aW2s[j], w1v = S.aW2s[j + 1];
                sr  += fmaxf(C2[jt][0] + b0v, 0.f) * w0v + fmaxf(C2[jt][1] + b1v, 0.f) * w1v;
                sr8 += fmaxf(C2[jt][2] + b0v, 0.f) * w0v + fmaxf(C2[jt][3] + b1v, 0.f) * w1v;
            }
            sr  += __shfl_xor_sync(0xffffffffu, sr, 1);
            sr  += __shfl_xor_sync(0xffffffffu, sr, 2);
            sr8 += __shfl_xor_sync(0xffffffffu, sr8, 1);
            sr8 += __shfl_xor_sync(0xffffffffu, sr8, 2);
            if (tig == 0) {
                S.scores[l0 + gid]     = sr + ab2v;
                S.scores[l0 + gid + 8] = sr8 + ab2v;
            }
        }
        __syncthreads();

        // ---- mask + softmax ----
        {
            float sv = -3.402823466e38f;
            if (tid < LSEQ) {
                sv = S.scores[tid];
                if (history_seq[b * LSEQ + tid] == 0) sv = -1.0e9f;
            }
            float v = sv;
            #pragma unroll
            for (int o = 16; o; o >>= 1) v = fmaxf(v, __shfl_xor_sync(0xffffffffu, v, o));
            if (lane == 0) S.red[w] = v;
            __syncthreads();
            if (tid < 32) {
                float r = (tid < 13) ? S.red[tid] : -3.402823466e38f;
                #pragma unroll
                for (int o = 8; o; o >>= 1) r = fmaxf(r, __shfl_xor_sync(0xffffffffu, r, o));
                if (tid == 0) S.red[13] = r;
            }
            __syncthreads();
            float mx = S.red[13];
            float e = (tid < LSEQ) ? expf(sv - mx) : 0.f;
            float v2 = e;
            #pragma unroll
            for (int o = 16; o; o >>= 1) v2 += __shfl_xor_sync(0xffffffffu, v2, o);
            if (lane == 0) S.red[w] = v2;
            __syncthreads();
            if (tid < 32) {
                float r = (tid < 13) ? S.red[tid] : 0.f;
                #pragma unroll
                for (int o = 8; o; o >>= 1) r += __shfl_xor_sync(0xffffffffu, r, o);
                if (tid == 0) S.red[13] = r;
            }
            __syncthreads();
            float inv = 1.f / S.red[13];
            if (tid < LSEQ) S.scores[tid] = e * inv;
        }
        __syncthreads();

        // ---- pooling (fp32, f32x2) ----
        {
            int kq = tid & 15, lg = tid >> 4;   // lg: 0..25
            int k4 = kq * 4;
            u64t a01 = 0ull, a23 = 0ull;
            for (int l = lg; l < LSEQ; l += 26) {
                u64t sd = dup2(S.scores[l]);
                ulonglong2 h = *(const ulonglong2*)&S.histL[l * HSTR + k4];
                fma2(a01, h.x, sd);
                fma2(a23, h.y, sd);
            }
            float p0, p1, p2, p3;
            unpack2(a01, p0, p1);
            unpack2(a23, p2, p3);
            S.poolbuf[lg * 64 + k4 + 0] = p0;
            S.poolbuf[lg * 64 + k4 + 1] = p1;
            S.poolbuf[lg * 64 + k4 + 2] = p2;
            S.poolbuf[lg * 64 + k4 + 3] = p3;
        }
        __syncthreads();
        if (tid < 64) {
            float p = 0.f;
            #pragma unroll
            for (int g = 0; g < 26; g++) p += S.poolbuf[g * 64 + tid];
            g_xbuf[b * 244 + 180 + tid] = p;
        }
        // ---- assemble x ----
        if (tid < 64) {
            g_xbuf[b * 244 + tid] = user_W[user_id[b] * 64 + tid];
        } else if (tid < 128) {
            g_xbuf[b * 244 + tid] = S.t[tid - 64];
        } else if (tid < 144) {
            g_xbuf[b * 244 + tid] = cat_W[item_category[b] * 16 + (tid - 128)];
        } else if (tid < 152) {
            g_xbuf[b * 244 + tid] = dur_W[item_dur_bkt[b] * 8 + (tid - 144)];
        } else if (tid < 177) {
            g_xbuf[b * 244 + tid] = user_dense[b * 25 + (tid - 152)];
        } else if (tid < 180) {
            g_xbuf[b * 244 + tid] = item_dense[b * 3 + (tid - 177)];
        }
        __syncthreads();   // histL/t/scores reuse before next sample
    }
}

// ---- MLP: 16 samples/block as two 8-sample groups, f32x2, 8-weight batches ----
__global__ __launch_bounds__(256, 2) void mlp_kernel(
    const float* __restrict__ mW0, const float* __restrict__ mb0,
    const float* __restrict__ mW1, const float* __restrict__ mb1,
    const float* __restrict__ mW2, const float* __restrict__ mb2,
    float* __restrict__ out, int B)
{
    __shared__ __align__(16) float xsA[244 * 8];
    __shared__ __align__(16) float xsB[244 * 8];
    __shared__ __align__(16) float h0A[256 * 8];
    __shared__ __align__(16) float h0B[256 * 8];
    __shared__ __align__(16) float h1s[16 * 128];
    const int b0 = blockIdx.x * 16;
    const int tid = threadIdx.x;

    #pragma unroll
    for (int q = 0; q < 8; q++) {
        if (tid < 244) {
            if (b0 + q < B)     xsA[tid * 8 + q] = g_xbuf[(b0 + q) * 244 + tid];
            if (b0 + 8 + q < B) xsB[tid * 8 + q] = g_xbuf[(b0 + 8 + q) * 244 + tid];
        }
    }
    __syncthreads();

    {
        u64t acc[8];
        u64t bias = dup2(mb0[tid]);
        #pragma unroll
        for (int p = 0; p < 8; p++) acc[p] = bias;
        #pragma unroll 1
        for (int i = 0; i < 240; i += 8) {
            float wv[8];
            #pragma unroll
            for (int u = 0; u < 8; u++) wv[u] = mW0[(i + u) * 256 + tid];
            #pragma unroll
            for (int u = 0; u < 8; u++) {
                u64t wd = dup2(wv[u]);
                ulonglong2 a01 = *(const ulonglong2*)&xsA[(i + u) * 8];
                ulonglong2 a23 = *(const ulonglong2*)&xsA[(i + u) * 8 + 4];
                ulonglong2 b01 = *(const ulonglong2*)&xsB[(i + u) * 8];
                ulonglong2 b23 = *(const ulonglong2*)&xsB[(i + u) * 8 + 4];
                fma2(acc[0], a01.x, wd); fma2(acc[1], a01.y, wd);
                fma2(acc[2], a23.x, wd); fma2(acc[3], a23.y, wd);
                fma2(acc[4], b01.x, wd); fma2(acc[5], b01.y, wd);
                fma2(acc[6], b23.x, wd); fma2(acc[7], b23.y, wd);
            }
        }
        #pragma unroll
        for (int i = 240; i < 244; i++) {
            u64t wd = dup2(mW0[i * 256 + tid]);
            ulonglong2 a01 = *(const ulonglong2*)&xsA[i * 8];
            ulonglong2 a23 = *(const ulonglong2*)&xsA[i * 8 + 4];
            ulonglong2 b01 = *(const ulonglong2*)&xsB[i * 8];
            ulonglong2 b23 = *(const ulonglong2*)&xsB[i * 8 + 4];
            fma2(acc[0], a01.x, wd); fma2(acc[1], a01.y, wd);
            fma2(acc[2], a23.x, wd); fma2(acc[3], a23.y, wd);
            fma2(acc[4], b01.x, wd); fma2(acc[5], b01.y, wd);
            fma2(acc[6], b23.x, wd); fma2(acc[7], b23.y, wd);
        }
        #pragma unroll
        for (int p = 0; p < 4; p++) {
            float a, c;
            unpack2(acc[p], a, c);
            h0A[tid * 8 + 2 * p]     = fmaxf(a, 0.f);
            h0A[tid * 8 + 2 * p + 1] = fmaxf(c, 0.f);
            unpack2(acc[4 + p], a, c);
            h0B[tid * 8 + 2 * p]     = fmaxf(a, 0.f);
            h0B[tid * 8 + 2 * p + 1] = fmaxf(c, 0.f);
        }
    }
    __syncthreads();

    {
        int j = tid & 127, h = tid >> 7;
        const float* h0p = h ? h0B : h0A;
        u64t bias = dup2(mb1[j]);
        u64t acc[4] = {bias, bias, bias, bias};
        #pragma unroll 1
        for (int i = 0; i < 256; i += 8) {
            float wv[8];
            #pragma unroll
            for (int u = 0; u < 8; u++) wv[u] = mW1[(i + u) * 128 + j];
            #pragma unroll
            for (int u = 0; u < 8; u++) {
                u64t wd = dup2(wv[u]);
                ulonglong2 a01 = *(const ulonglong2*)&h0p[(i + u) * 8];
                ulonglong2 a23 = *(const ulonglong2*)&h0p[(i + u) * 8 + 4];
                fma2(acc[0], a01.x, wd); fma2(acc[1], a01.y, wd);
                fma2(acc[2], a23.x, wd); fma2(acc[3], a23.y, wd);
            }
        }
        #pragma unroll
        for (int p = 0; p < 4; p++) {
            float a, c;
            unpack2(acc[p], a, c);
            h1s[(h * 8 + 2 * p) * 128 + j]     = fmaxf(a, 0.f);
            h1s[(h * 8 + 2 * p + 1) * 128 + j] = fmaxf(c, 0.f);
        }
    }
    __syncthreads();

    {
        int wsel = tid >> 5, lane = tid & 31;
        float m0 = mW2[lane], m1 = mW2[lane + 32], m2 = mW2[lane + 64], m3 = mW2[lane + 96];
        #pragma unroll
        for (int g = 0; g < 2; g++) {
            int sidx = wsel + g * 8;
            const float* hp = &h1s[sidx * 128];
            float v = hp[lane] * m0 + hp[lane + 32] * m1 + hp[lane + 64] * m2 + hp[lane + 96] * m3;
            #pragma unroll
            for (int o = 16; o; o >>= 1) v += __shfl_xor_sync(0xffffffffu, v, o);
            if (lane == 0 && (b0 + sidx) < B) {
                float logit = v + mb2[0];
                out[b0 + sidx] = 1.f / (1.f + expf(-logit));
            }
        }
    }
}

extern "C" void kernel_launch(void* const* d_in, const int* in_sizes, int n_in,
                              void* d_out, int out_size)
{
    const int*   user_id       = (const int*)d_in[0];
    const int*   item_id       = (const int*)d_in[1];
    const int*   item_category = (const int*)d_in[2];
    const int*   item_dur_bkt  = (const int*)d_in[3];
    const float* user_dense    = (const float*)d_in[4];
    const float* item_dense    = (const float*)d_in[5];
    const int*   history_seq   = (const int*)d_in[6];
    const float* user_W        = (const float*)d_in[7];
    const float* item_W        = (const float*)d_in[8];
    const float* cat_W         = (const float*)d_in[9];
    const float* dur_W         = (const float*)d_in[10];
    const float* hist_W        = (const float*)d_in[11];
    const float* aW0 = (const float*)d_in[12];
    const float* ab0 = (const float*)d_in[13];
    const float* aW1 = (const float*)d_in[14];
    const float* ab1 = (const float*)d_in[15];
    const float* aW2 = (const float*)d_in[16];
    const float* ab2 = (const float*)d_in[17];
    const float* mW0 = (const float*)d_in[18];
    const float* mb0 = (const float*)d_in[19];
    const float* mW1 = (const float*)d_in[20];
    const float* mb1 = (const float*)d_in[21];
    const float* mW2 = (const float*)d_in[22];
    const float* mb2 = (const float*)d_in[23];

    const int B = in_sizes[0];
    float* out = (float*)d_out;

    precompute_kernel<<<16, 256>>>(aW0, aW1);

    cudaFuncSetAttribute(attn_kernel, cudaFuncAttributeMaxDynamicSharedMemorySize,
                         (int)sizeof(SmemA));

    attn_kernel<<<(B + SAMPLES - 1) / SAMPLES, NTHR, sizeof(SmemA)>>>(
        user_id, item_id, item_category, item_dur_bkt,
        user_dense, item_dense, history_seq,
        user_W, item_W, cat_W, dur_W, hist_W,
        ab0, ab1, aW2, ab2, B);

    mlp_kernel<<<(B + 15) / 16, 256>>>(mW0, mb0, mW1, mb1, mW2, mb2, out, B);
}

// round 14
// speedup vs baseline: 1.1343x; 1.0769x over previous
#include <cuda_runtime.h>
#include <math.h>

#define LSEQ 200
#define HSTR 68      // histL row stride (floats)
#define MP_STR 68    // Mp row stride (uint2)
#define W1P_STR 36   // W1p row stride (uint2)
#define NTHR 416     // 13 warps
#define SAMPLES 4
#define B_MAX 4096

__device__ float g_xbuf[B_MAX * 244];
__device__ __align__(16) unsigned int g_B3p[32 * 64 * 2];       // W_t - W_d packed tf32 pairs
__device__ __align__(16) unsigned int g_W1p[32 * W1P_STR * 2];  // aW1 packed tf32 pairs

typedef unsigned long long u64t;
typedef unsigned int u32t;

__device__ __forceinline__ u64t dup2(float x) {
    u64t r; asm("mov.b64 %0, {%1, %1};" : "=l"(r) : "f"(x)); return r;
}
__device__ __forceinline__ void fma2(u64t& d, u64t a, u64t b) {
    asm("fma.rn.f32x2 %0, %1, %2, %0;" : "+l"(d) : "l"(a), "l"(b));
}
__device__ __forceinline__ void unpack2(u64t v, float& a, float& b) {
    asm("mov.b64 {%0, %1}, %2;" : "=f"(a), "=f"(b) : "l"(v));
}
__device__ __forceinline__ u32t f2tf32(float f) {
    u32t u; asm("cvt.rna.tf32.f32 %0, %1;" : "=r"(u) : "f"(f)); return u;
}
__device__ __forceinline__ void mma_tf32(float& d0, float& d1, float& d2, float& d3,
                                         u32t a0, u32t a1, u32t a2, u32t a3,
                                         u32t b0, u32t b1) {
    asm volatile(
        "mma.sync.aligned.m16n8k8.row.col.f32.tf32.tf32.f32 "
        "{%0,%1,%2,%3},{%4,%5,%6,%7},{%8,%9},{%0,%1,%2,%3};"
        : "+f"(d0), "+f"(d1), "+f"(d2), "+f"(d3)
        : "r"(a0), "r"(a1), "r"(a2), "r"(a3), "r"(b0), "r"(b1));
}

// ---- precompute static tf32-packed weights ----
__global__ void precompute_kernel(const float* __restrict__ aW0,
                                  const float* __restrict__ aW1)
{
    int idx = blockIdx.x * blockDim.x + threadIdx.x;
    int stride = gridDim.x * blockDim.x;
    for (int p = idx; p < 4096; p += stride) {
        int k = p >> 6, j = p & 63;
        float b3 = aW0[(64 + k) * 64 + j] - aW0[(192 + k) * 64 + j];
        int kt = k >> 3, r = k & 7, tg = r & 3, half = r >> 2;
        g_B3p[(((kt * 4 + tg) * 64) + j) * 2 + half] = f2tf32(b3);
    }
    for (int p = idx; p < 2048; p += stride) {
        int k = p >> 5, j = p & 31;
        int kt = k >> 3, r = k & 7, tg = r & 3, half = r >> 2;
        g_W1p[(((kt * 4 + tg) * W1P_STR) + j) * 2 + half] = f2tf32(aW1[p]);
    }
}

struct __align__(16) SmemA {
    float histL[208 * HSTR];     // 56576 B
    uint2 Mp[32 * MP_STR];       // 17408 B (per-sample M, tf32 packed)
    uint2 W1p[32 * W1P_STR];     // 9216 B
    float t[64];
    float ab0s[64];
    float cbias[64];
    float ab1s[32];
    float aW2s[32];
    float scores[208];
    float red[16];
    float poolbuf[26 * 64];      // 6656 B
};

__global__ __launch_bounds__(NTHR, 2) void attn_kernel(
    const int* __restrict__ user_id, const int* __restrict__ item_id,
    const int* __restrict__ item_category, const int* __restrict__ item_dur_bkt,
    const float* __restrict__ user_dense, const float* __restrict__ item_dense,
    const int* __restrict__ history_seq,
    const float* __restrict__ user_W, const float* __restrict__ item_W,
    const float* __restrict__ cat_W, const float* __restrict__ dur_W,
    const float* __restrict__ hist_W,
    const float* __restrict__ aW0, const float* __restrict__ ab0,
    const float* __restrict__ ab1, const float* __restrict__ aW2,
    const float* __restrict__ ab2, int B)
{
    extern __shared__ char smem_raw[];
    SmemA& S = *reinterpret_cast<SmemA*>(smem_raw);
    float* Mpf = (float*)S.Mp;
    const int tid = threadIdx.x;
    const int lane = tid & 31;
    const int w = tid >> 5;            // 0..12

    const int gid = lane >> 2;   // 0..7
    const int tig = lane & 3;    // 0..3
    const bool odd = tig & 1;
    const int src0 = gid * 4 + (tig >> 1);
    const int src2 = src0 + 2;
    const float ab2v = ab2[0];

    // ---- once-per-block staging ----
    for (int i = tid; i < 576; i += NTHR)
        ((uint4*)S.W1p)[i] = ((const uint4*)g_W1p)[i];
    if (tid < 64) S.ab0s[tid] = ab0[tid];
    else if (tid < 96) { S.aW2s[tid - 64] = aW2[tid - 64]; S.ab1s[tid - 64] = ab1[tid - 64]; }
    for (int p = tid; p < 8 * 64; p += NTHR)
        S.histL[(LSEQ + (p >> 6)) * HSTR + (p & 63)] = 0.f;
    __syncthreads();

    for (int s = 0; s < SAMPLES; s++) {
        int b = blockIdx.x * SAMPLES + s;
        if (b >= B) b = B - 1;
        const int iid = item_id[b];

        // ===== merged phase: t + gather + Mp build + cbias (t via gmem) =====
        if (tid < 64) S.t[tid] = item_W[iid * 64 + tid];
        {
            int c8 = tid & 7, lb = tid >> 3;   // lb: 0..51
            const int* hs = &history_seq[b * LSEQ];
            int r0 = hs[lb];
            int r1 = hs[lb + 52];
            int r2 = hs[lb + 104];
            bool has3 = (lb + 156) < LSEQ;
            int r3 = has3 ? hs[lb + 156] : 0;
            const float4* p0 = (const float4*)&hist_W[r0 * 64] + c8 * 2;
            const float4* p1 = (const float4*)&hist_W[r1 * 64] + c8 * 2;
            const float4* p2 = (const float4*)&hist_W[r2 * 64] + c8 * 2;
            const float4* p3 = (const float4*)&hist_W[r3 * 64] + c8 * 2;
            float4 a0 = p0[0], a1 = p0[1];
            float4 b0 = p1[0], b1 = p1[1];
            float4 c0 = p2[0], c1 = p2[1];
            float4 d0 = p3[0], d1 = p3[1];
            float* dst0 = &S.histL[lb * HSTR + c8 * 8];
            *(float4*)dst0 = a0; *(float4*)(dst0 + 4) = a1;
            float* dst1 = &S.histL[(lb + 52) * HSTR + c8 * 8];
            *(float4*)dst1 = b0; *(float4*)(dst1 + 4) = b1;
            float* dst2 = &S.histL[(lb + 104) * HSTR + c8 * 8];
            *(float4*)dst2 = c0; *(float4*)(dst2 + 4) = c1;
            if (has3) {
                float* dst3 = &S.histL[(lb + 156) * HSTR + c8 * 8];
                *(float4*)dst3 = d0; *(float4*)(dst3 + 4) = d1;
            }
        }
        // Mp build: t read from gmem (no sync needed)
        for (int g4 = tid; g4 < 1024; g4 += NTHR) {
            int k = g4 >> 4, j4 = (g4 & 15) << 2;
            float tk = __ldg(&item_W[iid * 64 + k]);
            float4 a0v  = *(const float4*)&aW0[k * 64 + j4];
            float4 a192 = *(const float4*)&aW0[(192 + k) * 64 + j4];
            float4 a128 = *(const float4*)&aW0[(128 + k) * 64 + j4];
            int kt = k >> 3, r = k & 7, tg = r & 3, half = r >> 2;
            float* dst = &Mpf[((kt * 4 + tg) * MP_STR) * 2 + half];
            dst[(j4 + 0) * 2] = __uint_as_float(f2tf32(a0v.x + a192.x + tk * a128.x));
            dst[(j4 + 1) * 2] = __uint_as_float(f2tf32(a0v.y + a192.y + tk * a128.y));
            dst[(j4 + 2) * 2] = __uint_as_float(f2tf32(a0v.z + a192.z + tk * a128.z));
            dst[(j4 + 3) * 2] = __uint_as_float(f2tf32(a0v.w + a192.w + tk * a128.w));
        }
        // cbias via MMA (warps 0..7), t read from gmem
        if (w < 8) {
            float d0 = 0.f, d1 = 0.f, d2 = 0.f, d3 = 0.f;
            #pragma unroll
            for (int kt = 0; kt < 8; kt++) {
                u32t ua0 = f2tf32(__ldg(&item_W[iid * 64 + kt * 8 + tig]));
                u32t ua2 = f2tf32(__ldg(&item_W[iid * 64 + kt * 8 + tig + 4]));
                uint2 bb = ((const uint2*)g_B3p)[(kt * 4 + tig) * 64 + w * 8 + gid];
                mma_tf32(d0, d1, d2, d3, ua0, ua0, ua2, ua2, bb.x, bb.y);
            }
            if (gid == 0) {
                S.cbias[w * 8 + 2 * tig]     = S.ab0s[w * 8 + 2 * tig] + d0;
                S.cbias[w * 8 + 2 * tig + 1] = S.ab0s[w * 8 + 2 * tig + 1] + d1;
            }
        }
        __syncthreads();

        // ===== mainloop: warp w owns l-tile w =====
        {
            const int l0 = w * 16;

            float C1[8][4] = {};
            #pragma unroll
            for (int kt = 0; kt < 8; kt++) {
                const float* ap = &S.histL[(l0 + gid) * HSTR + kt * 8 + tig];
                u32t ua0 = f2tf32(ap[0]);
                u32t ua1 = f2tf32(ap[8 * HSTR]);
                u32t ua2 = f2tf32(ap[4]);
                u32t ua3 = f2tf32(ap[8 * HSTR + 4]);
                const uint2* bp = &S.Mp[(kt * 4 + tig) * MP_STR + gid];
                #pragma unroll
                for (int jt = 0; jt < 8; jt++) {
                    uint2 bb = bp[jt * 8];
                    mma_tf32(C1[jt][0], C1[jt][1], C1[jt][2], C1[jt][3],
                             ua0, ua1, ua2, ua3, bb.x, bb.y);
                }
            }
            #pragma unroll
            for (int jt = 0; jt < 8; jt++) {
                float cb0 = S.cbias[jt * 8 + 2 * tig], cb1 = S.cbias[jt * 8 + 2 * tig + 1];
                C1[jt][0] = fmaxf(C1[jt][0] + cb0, 0.f);
                C1[jt][1] = fmaxf(C1[jt][1] + cb1, 0.f);
                C1[jt][2] = fmaxf(C1[jt][2] + cb0, 0.f);
                C1[jt][3] = fmaxf(C1[jt][3] + cb1, 0.f);
            }

            float C2[4][4] = {};
            #pragma unroll
            for (int kt = 0; kt < 8; kt++) {
                float v00 = __shfl_sync(0xffffffffu, C1[kt][0], src0);
                float v01 = __shfl_sync(0xffffffffu, C1[kt][1], src0);
                float v10 = __shfl_sync(0xffffffffu, C1[kt][2], src0);
                float v11 = __shfl_sync(0xffffffffu, C1[kt][3], src0);
                float v20 = __shfl_sync(0xffffffffu, C1[kt][0], src2);
                float v21 = __shfl_sync(0xffffffffu, C1[kt][1], src2);
                float v30 = __shfl_sync(0xffffffffu, C1[kt][2], src2);
                float v31 = __shfl_sync(0xffffffffu, C1[kt][3], src2);
                u32t ua0 = f2tf32(odd ? v01 : v00);
                u32t ua1 = f2tf32(odd ? v11 : v10);
                u32t ua2 = f2tf32(odd ? v21 : v20);
                u32t ua3 = f2tf32(odd ? v31 : v30);
                const uint2* bp = &S.W1p[(kt * 4 + tig) * W1P_STR + gid];
                #pragma unroll
                for (int jt = 0; jt < 4; jt++) {
                    uint2 bb = bp[jt * 8];
                    mma_tf32(C2[jt][0], C2[jt][1], C2[jt][2], C2[jt][3],
                             ua0, ua1, ua2, ua3, bb.x, bb.y);
                }
            }
            float sr = 0.f, sr8 = 0.f;
            #pragma unroll
            for (int jt = 0; jt < 4; jt++) {
                int j = jt * 8 + 2 * tig;
                float b0v = S.ab1s[j], b1v = S.ab1s[j + 1];
                float w0v = S.aW2s[j], w1v = S.aW2s[j + 1];
                sr  += fmaxf(C2[jt][0] + b0v, 0.f) * w0v + fmaxf(C2[jt][1] + b1v, 0.f) * w1v;
                sr8 += fmaxf(C2[jt][2] + b0v, 0.f) * w0v + fmaxf(C2[jt][3] + b1v, 0.f) * w1v;
            }
            sr  += __shfl_xor_sync(0xffffffffu, sr, 1);
            sr  += __shfl_xor_sync(0xffffffffu, sr, 2);
            sr8 += __shfl_xor_sync(0xffffffffu, sr8, 1);
            sr8 += __shfl_xor_sync(0xffffffffu, sr8, 2);
            if (tig == 0) {
                S.scores[l0 + gid]     = sr + ab2v;
                S.scores[l0 + gid + 8] = sr8 + ab2v;
            }
        }
        __syncthreads();

        // ===== softmax (e-trick: pool unnormalized, scale later) =====
        {
            float sv = -3.402823466e38f;
            if (tid < LSEQ) {
                sv = S.scores[tid];
                if (history_seq[b * LSEQ + tid] == 0) sv = -1.0e9f;
            }
            float v = sv;
            #pragma unroll
            for (int o = 16; o; o >>= 1) v = fmaxf(v, __shfl_xor_sync(0xffffffffu, v, o));
            if (lane == 0) S.red[w] = v;
            __syncthreads();
            if (tid < 32) {
                float r = (tid < 13) ? S.red[tid] : -3.402823466e38f;
                #pragma unroll
                for (int o = 8; o; o >>= 1) r = fmaxf(r, __shfl_xor_sync(0xffffffffu, r, o));
                if (tid == 0) S.red[13] = r;
            }
            __syncthreads();
            float mx = S.red[13];
            float e = (tid < LSEQ) ? expf(sv - mx) : 0.f;
            if (tid < 208) S.scores[tid] = e;   // unnormalized weights; 200..207 -> 0
            float v2 = e;
            #pragma unroll
            for (int o = 16; o; o >>= 1) v2 += __shfl_xor_sync(0xffffffffu, v2, o);
            if (lane == 0) S.red[w] = v2;
        }
        __syncthreads();

        // ===== pooling with e (all threads) + final sum (warp 0, concurrent) =====
        if (tid < 32) {
            float r = (tid < 13) ? S.red[tid] : 0.f;
            #pragma unroll
            for (int o = 8; o; o >>= 1) r += __shfl_xor_sync(0xffffffffu, r, o);
            if (tid == 0) S.red[14] = r;
        }
        {
            int kq = tid & 15, lg = tid >> 4;   // lg: 0..25
            int k4 = kq * 4;
            u64t a01 = 0ull, a23 = 0ull;
            for (int l = lg; l < LSEQ; l += 26) {
                u64t sd = dup2(S.scores[l]);
                ulonglong2 h = *(const ulonglong2*)&S.histL[l * HSTR + k4];
                fma2(a01, h.x, sd);
                fma2(a23, h.y, sd);
            }
            float p0, p1, p2, p3;
            unpack2(a01, p0, p1);
            unpack2(a23, p2, p3);
            S.poolbuf[lg * 64 + k4 + 0] = p0;
            S.poolbuf[lg * 64 + k4 + 1] = p1;
            S.poolbuf[lg * 64 + k4 + 2] = p2;
            S.poolbuf[lg * 64 + k4 + 3] = p3;
        }
        __syncthreads();
        if (tid < 64) {
            float p = 0.f;
            #pragma unroll
            for (int g = 0; g < 26; g++) p += S.poolbuf[g * 64 + tid];
            g_xbuf[b * 244 + 180 + tid] = p * (1.f / S.red[14]);
        }
        // ---- assemble x ----
        if (tid < 64) {
            g_xbuf[b * 244 + tid] = user_W[user_id[b] * 64 + tid];
        } else if (tid < 128) {
            g_xbuf[b * 244 + tid] = S.t[tid - 64];
        } else if (tid < 144) {
            g_xbuf[b * 244 + tid] = cat_W[item_category[b] * 16 + (tid - 128)];
        } else if (tid < 152) {
            g_xbuf[b * 244 + tid] = dur_W[item_dur_bkt[b] * 8 + (tid - 144)];
        } else if (tid < 177) {
            g_xbuf[b * 244 + tid] = user_dense[b * 25 + (tid - 152)];
        } else if (tid < 180) {
            g_xbuf[b * 244 + tid] = item_dense[b * 3 + (tid - 177)];
        }
        __syncthreads();   // protect histL/t/Mp/scores before next sample
    }
}

// ---- MLP: 16 samples/block, 512 threads (two 8-sample groups in parallel) ----
__global__ __launch_bounds__(512, 2) void mlp_kernel(
    const float* __restrict__ mW0, const float* __restrict__ mb0,
    const float* __restrict__ mW1, const float* __restrict__ mb1,
    const float* __restrict__ mW2, const float* __restrict__ mb2,
    float* __restrict__ out, int B)
{
    __shared__ __align__(16) float xsA[244 * 8];
    __shared__ __align__(16) float xsB[244 * 8];
    __shared__ __align__(16) float h0A[256 * 8];
    __shared__ __align__(16) float h0B[256 * 8];
    __shared__ __align__(16) float h1s[16 * 128];
    const int b0 = blockIdx.x * 16;
    const int tid = threadIdx.x;

    {
        int g = tid >> 8, r = tid & 255;      // g: 0/1, r: 0..255
        float* xs = g ? xsB : xsA;
        int base = b0 + g * 8;
        if (r < 244) {
            #pragma unroll
            for (int q = 0; q < 8; q++)
                if (base + q < B) xs[r * 8 + q] = g_xbuf[(base + q) * 244 + r];
        }
    }
    __syncthreads();

    // layer 0: 244 -> 256; group g handles 8 samples, col = tid&255
    {
        int g = tid >> 8, col = tid & 255;
        const float* xs = g ? xsB : xsA;
        float* h0 = g ? h0B : h0A;
        u64t acc[4];
        u64t bias = dup2(mb0[col]);
        #pragma unroll
        for (int p = 0; p < 4; p++) acc[p] = bias;
        #pragma unroll 1
        for (int i = 0; i < 240; i += 8) {
            float wv[8];
            #pragma unroll
            for (int u = 0; u < 8; u++) wv[u] = mW0[(i + u) * 256 + col];
            #pragma unroll
            for (int u = 0; u < 8; u++) {
                u64t wd = dup2(wv[u]);
                ulonglong2 a01 = *(const ulonglong2*)&xs[(i + u) * 8];
                ulonglong2 a23 = *(const ulonglong2*)&xs[(i + u) * 8 + 4];
                fma2(acc[0], a01.x, wd); fma2(acc[1], a01.y, wd);
                fma2(acc[2], a23.x, wd); fma2(acc[3], a23.y, wd);
            }
        }
        #pragma unroll
        for (int i = 240; i < 244; i++) {
            u64t wd = dup2(mW0[i * 256 + col]);
            ulonglong2 a01 = *(const ulonglong2*)&xs[i * 8];
            ulonglong2 a23 = *(const ulonglong2*)&xs[i * 8 + 4];
            fma2(acc[0], a01.x, wd); fma2(acc[1], a01.y, wd);
            fma2(acc[2], a23.x, wd); fma2(acc[3], a23.y, wd);
        }
        #pragma unroll
        for (int p = 0; p < 4; p++) {
            float a, c;
            unpack2(acc[p], a, c);
            h0[col * 8 + 2 * p]     = fmaxf(a, 0.f);
            h0[col * 8 + 2 * p + 1] = fmaxf(c, 0.f);
        }
    }
    __syncthreads();

    // layer 1: 256 -> 128; quarter q = tid>>7 handles 4 samples
    {
        int j = tid & 127, q = tid >> 7;     // q: 0..3
        int g = q >> 1, h = q & 1;
        const float* h0p = g ? h0B : h0A;
        u64t bias = dup2(mb1[j]);
        u64t acc[2] = {bias, bias};
        #pragma unroll 1
        for (int i = 0; i < 256; i += 8) {
            float wv[8];
            #pragma unroll
            for (int u = 0; u < 8; u++) wv[u] = mW1[(i + u) * 128 + j];
            #pragma unroll
            for (int u = 0; u < 8; u++) {
                u64t wd = dup2(wv[u]);
                ulonglong2 a01 = *(const ulonglong2*)&h0p[(i + u) * 8 + h * 4];
                fma2(acc[0], a01.x, wd); fma2(acc[1], a01.y, wd);
            }
        }
        int srow = g * 8 + h * 4;
        #pragma unroll
        for (int p = 0; p < 2; p++) {
            float a, c;
            unpack2(acc[p], a, c);
            h1s[(srow + 2 * p) * 128 + j]     = fmaxf(a, 0.f);
            h1s[(srow + 2 * p + 1) * 128 + j] = fmaxf(c, 0.f);
        }
    }
    __syncthreads();

    // layer 2: 128 -> 1, sigmoid; 16 warps, one sample each
    {
        int wsel = tid >> 5, lane = tid & 31;
        float m0 = mW2[lane], m1 = mW2[lane + 32], m2 = mW2[lane + 64], m3 = mW2[lane + 96];
        const float* hp = &h1s[wsel * 128];
        float v = hp[lane] * m0 + hp[lane + 32] * m1 + hp[lane + 64] * m2 + hp[lane + 96] * m3;
        #pragma unroll
        for (int o = 16; o; o >>= 1) v += __shfl_xor_sync(0xffffffffu, v, o);
        if (lane == 0 && (b0 + wsel) < B) {
            float logit = v + mb2[0];
            out[b0 + wsel] = 1.f / (1.f + expf(-logit));
        }
    }
}

extern "C" void kernel_launch(void* const* d_in, const int* in_sizes, int n_in,
                              void* d_out, int out_size)
{
    const int*   user_id       = (const int*)d_in[0];
    const int*   item_id       = (const int*)d_in[1];
    const int*   item_category = (const int*)d_in[2];
    const int*   item_dur_bkt  = (const int*)d_in[3];
    const float* user_dense    = (const float*)d_in[4];
    const float* item_dense    = (const float*)d_in[5];
    const int*   history_seq   = (const int*)d_in[6];
    const float* user_W        = (const float*)d_in[7];
    const float* item_W        = (const float*)d_in[8];
    const float* cat_W         = (const float*)d_in[9];
    const float* dur_W         = (const float*)d_in[10];
    const float* hist_W        = (const float*)d_in[11];
    const float* aW0 = (const float*)d_in[12];
    const float* ab0 = (const float*)d_in[13];
    const float* aW1 = (const float*)d_in[14];
    const float* ab1 = (const float*)d_in[15];
    const float* aW2 = (const float*)d_in[16];
    const float* ab2 = (const float*)d_in[17];
    const float* mW0 = (const float*)d_in[18];
    const float* mb0 = (const float*)d_in[19];
    const float* mW1 = (const float*)d_in[20];
    const float* mb1 = (const float*)d_in[21];
    const float* mW2 = (const float*)d_in[22];
    const float* mb2 = (const float*)d_in[23];

    const int B = in_sizes[0];
    float* out = (float*)d_out;

    precompute_kernel<<<16, 256>>>(aW0, aW1);

    cudaFuncSetAttribute(attn_kernel, cudaFuncAttributeMaxDynamicSharedMemorySize,
                         (int)sizeof(SmemA));

    attn_kernel<<<(B + SAMPLES - 1) / SAMPLES, NTHR, sizeof(SmemA)>>>(
        user_id, item_id, item_category, item_dur_bkt,
        user_dense, item_dense, history_seq,
        user_W, item_W, cat_W, dur_W, hist_W,
        aW0, ab0, ab1, aW2, ab2, B);

    mlp_kernel<<<(B + 15) / 16, 512>>>(mW0, mb0, mW1, mb1, mW2, mb2, out, B);
}

// round 15
// speedup vs baseline: 1.1796x; 1.0399x over previous
#include <cuda_runtime.h>
#include <math.h>

#define LSEQ 200
#define HSTR 68      // histL row stride (floats)
#define MP_STR 68    // Mp row stride (uint2)
#define W1P_STR 36   // W1p row stride (uint2)
#define NTHR 416     // 13 warps
#define SAMPLES 4
#define B_MAX 4096

__device__ float g_xbuf[B_MAX * 244];
__device__ __align__(16) unsigned int g_B3p[32 * 64 * 2];       // W_t - W_d packed tf32 pairs
__device__ __align__(16) unsigned int g_W1p[32 * W1P_STR * 2];  // aW1 packed tf32 pairs

typedef unsigned long long u64t;
typedef unsigned int u32t;

__device__ __forceinline__ u64t dup2(float x) {
    u64t r; asm("mov.b64 %0, {%1, %1};" : "=l"(r) : "f"(x)); return r;
}
__device__ __forceinline__ void fma2(u64t& d, u64t a, u64t b) {
    asm("fma.rn.f32x2 %0, %1, %2, %0;" : "+l"(d) : "l"(a), "l"(b));
}
__device__ __forceinline__ void unpack2(u64t v, float& a, float& b) {
    asm("mov.b64 {%0, %1}, %2;" : "=f"(a), "=f"(b) : "l"(v));
}
__device__ __forceinline__ u32t f2tf32(float f) {
    u32t u; asm("cvt.rna.tf32.f32 %0, %1;" : "=r"(u) : "f"(f)); return u;
}
__device__ __forceinline__ void mma_tf32(float& d0, float& d1, float& d2, float& d3,
                                         u32t a0, u32t a1, u32t a2, u32t a3,
                                         u32t b0, u32t b1) {
    asm volatile(
        "mma.sync.aligned.m16n8k8.row.col.f32.tf32.tf32.f32 "
        "{%0,%1,%2,%3},{%4,%5,%6,%7},{%8,%9},{%0,%1,%2,%3};"
        : "+f"(d0), "+f"(d1), "+f"(d2), "+f"(d3)
        : "r"(a0), "r"(a1), "r"(a2), "r"(a3), "r"(b0), "r"(b1));
}

// ---- precompute static tf32-packed weights ----
__global__ void precompute_kernel(const float* __restrict__ aW0,
                                  const float* __restrict__ aW1)
{
    int idx = blockIdx.x * blockDim.x + threadIdx.x;
    int stride = gridDim.x * blockDim.x;
    for (int p = idx; p < 4096; p += stride) {
        int k = p >> 6, j = p & 63;
        float b3 = aW0[(64 + k) * 64 + j] - aW0[(192 + k) * 64 + j];
        int kt = k >> 3, r = k & 7, tg = r & 3, half = r >> 2;
        g_B3p[(((kt * 4 + tg) * 64) + j) * 2 + half] = f2tf32(b3);
    }
    for (int p = idx; p < 2048; p += stride) {
        int k = p >> 5, j = p & 31;
        int kt = k >> 3, r = k & 7, tg = r & 3, half = r >> 2;
        g_W1p[(((kt * 4 + tg) * W1P_STR) + j) * 2 + half] = f2tf32(aW1[p]);
    }
}

struct __align__(16) SmemA {
    float histL[208 * HSTR];     // 56576 B
    uint2 Mp[32 * MP_STR];       // 17408 B (per-sample M, tf32 packed)
    uint2 W1p[32 * W1P_STR];     // 9216 B
    float t[64];
    float ab0s[64];
    float cbias[64];
    float ab1s[32];
    float aW2s[32];
    float scores[208];
    float red[16];
    float poolbuf[26 * 64];      // 6656 B
};

__global__ __launch_bounds__(NTHR, 2) void attn_kernel(
    const int* __restrict__ user_id, const int* __restrict__ item_id,
    const int* __restrict__ item_category, const int* __restrict__ item_dur_bkt,
    const float* __restrict__ user_dense, const float* __restrict__ item_dense,
    const int* __restrict__ history_seq,
    const float* __restrict__ user_W, const float* __restrict__ item_W,
    const float* __restrict__ cat_W, const float* __restrict__ dur_W,
    const float* __restrict__ hist_W,
    const float* __restrict__ aW0, const float* __restrict__ ab0,
    const float* __restrict__ ab1, const float* __restrict__ aW2,
    const float* __restrict__ ab2, int B)
{
    extern __shared__ char smem_raw[];
    SmemA& S = *reinterpret_cast<SmemA*>(smem_raw);
    float* Mpf = (float*)S.Mp;
    const int tid = threadIdx.x;
    const int lane = tid & 31;
    const int w = tid >> 5;            // 0..12

    const int gid = lane >> 2;   // 0..7
    const int tig = lane & 3;    // 0..3
    const bool odd = tig & 1;
    const int src0 = gid * 4 + (tig >> 1);
    const int src2 = src0 + 2;
    const float ab2v = ab2[0];

    // ---- once-per-block staging ----
    for (int i = tid; i < 576; i += NTHR)
        ((uint4*)S.W1p)[i] = ((const uint4*)g_W1p)[i];
    if (tid < 64) S.ab0s[tid] = ab0[tid];
    else if (tid < 96) { S.aW2s[tid - 64] = aW2[tid - 64]; S.ab1s[tid - 64] = ab1[tid - 64]; }
    for (int p = tid; p < 8 * 64; p += NTHR)
        S.histL[(LSEQ + (p >> 6)) * HSTR + (p & 63)] = 0.f;
    // prefetch first sample's gather rows to L2
    {
        int b0 = blockIdx.x * SAMPLES;
        if (b0 < B && tid < LSEQ) {
            int rn = history_seq[b0 * LSEQ + tid];
            const char* pp = (const char*)&hist_W[rn * 64];
            asm volatile("prefetch.global.L2 [%0];" :: "l"(pp));
            asm volatile("prefetch.global.L2 [%0];" :: "l"(pp + 128));
        }
    }
    __syncthreads();

    for (int s = 0; s < SAMPLES; s++) {
        int b = blockIdx.x * SAMPLES + s;
        if (b >= B) b = B - 1;
        const int iid = item_id[b];

        // ===== merged phase: t + gather + prefetch(s+1) + Mp build + cbias =====
        if (tid < 64) S.t[tid] = item_W[iid * 64 + tid];
        {
            int c8 = tid & 7, lb = tid >> 3;   // lb: 0..51
            const int* hs = &history_seq[b * LSEQ];
            int r0 = hs[lb];
            int r1 = hs[lb + 52];
            int r2 = hs[lb + 104];
            bool has3 = (lb + 156) < LSEQ;
            int r3 = has3 ? hs[lb + 156] : 0;
            const float4* p0 = (const float4*)&hist_W[r0 * 64] + c8 * 2;
            const float4* p1 = (const float4*)&hist_W[r1 * 64] + c8 * 2;
            const float4* p2 = (const float4*)&hist_W[r2 * 64] + c8 * 2;
            const float4* p3 = (const float4*)&hist_W[r3 * 64] + c8 * 2;
            float4 a0 = p0[0], a1 = p0[1];
            float4 b0 = p1[0], b1 = p1[1];
            float4 c0 = p2[0], c1 = p2[1];
            float4 d0 = p3[0], d1 = p3[1];
            float* dst0 = &S.histL[lb * HSTR + c8 * 8];
            *(float4*)dst0 = a0; *(float4*)(dst0 + 4) = a1;
            float* dst1 = &S.histL[(lb + 52) * HSTR + c8 * 8];
            *(float4*)dst1 = b0; *(float4*)(dst1 + 4) = b1;
            float* dst2 = &S.histL[(lb + 104) * HSTR + c8 * 8];
            *(float4*)dst2 = c0; *(float4*)(dst2 + 4) = c1;
            if (has3) {
                float* dst3 = &S.histL[(lb + 156) * HSTR + c8 * 8];
                *(float4*)dst3 = d0; *(float4*)(dst3 + 4) = d1;
            }
        }
        // prefetch next sample's hist rows into L2 (hides DRAM latency)
        if (s + 1 < SAMPLES) {
            int bn = blockIdx.x * SAMPLES + s + 1;
            if (bn < B && tid < LSEQ) {
                int rn = history_seq[bn * LSEQ + tid];
                const char* pp = (const char*)&hist_W[rn * 64];
                asm volatile("prefetch.global.L2 [%0];" :: "l"(pp));
                asm volatile("prefetch.global.L2 [%0];" :: "l"(pp + 128));
            }
        }
        // Mp build: t read from gmem (no sync needed)
        for (int g4 = tid; g4 < 1024; g4 += NTHR) {
            int k = g4 >> 4, j4 = (g4 & 15) << 2;
            float tk = __ldg(&item_W[iid * 64 + k]);
            float4 a0v  = *(const float4*)&aW0[k * 64 + j4];
            float4 a192 = *(const float4*)&aW0[(192 + k) * 64 + j4];
            float4 a128 = *(const float4*)&aW0[(128 + k) * 64 + j4];
            int kt = k >> 3, r = k & 7, tg = r & 3, half = r >> 2;
            float* dst = &Mpf[((kt * 4 + tg) * MP_STR) * 2 + half];
            dst[(j4 + 0) * 2] = __uint_as_float(f2tf32(a0v.x + a192.x + tk * a128.x));
            dst[(j4 + 1) * 2] = __uint_as_float(f2tf32(a0v.y + a192.y + tk * a128.y));
            dst[(j4 + 2) * 2] = __uint_as_float(f2tf32(a0v.z + a192.z + tk * a128.z));
            dst[(j4 + 3) * 2] = __uint_as_float(f2tf32(a0v.w + a192.w + tk * a128.w));
        }
        // cbias via MMA (warps 0..7), t read from gmem
        if (w < 8) {
            float d0 = 0.f, d1 = 0.f, d2 = 0.f, d3 = 0.f;
            #pragma unroll
            for (int kt = 0; kt < 8; kt++) {
                u32t ua0 = f2tf32(__ldg(&item_W[iid * 64 + kt * 8 + tig]));
                u32t ua2 = f2tf32(__ldg(&item_W[iid * 64 + kt * 8 + tig + 4]));
                uint2 bb = ((const uint2*)g_B3p)[(kt * 4 + tig) * 64 + w * 8 + gid];
                mma_tf32(d0, d1, d2, d3, ua0, ua0, ua2, ua2, bb.x, bb.y);
            }
            if (gid == 0) {
                S.cbias[w * 8 + 2 * tig]     = S.ab0s[w * 8 + 2 * tig] + d0;
                S.cbias[w * 8 + 2 * tig + 1] = S.ab0s[w * 8 + 2 * tig + 1] + d1;
            }
        }
        __syncthreads();

        // ===== mainloop: warp w owns l-tile w =====
        {
            const int l0 = w * 16;

            float C1[8][4] = {};
            #pragma unroll
            for (int kt = 0; kt < 8; kt++) {
                const float* ap = &S.histL[(l0 + gid) * HSTR + kt * 8 + tig];
                u32t ua0 = f2tf32(ap[0]);
                u32t ua1 = f2tf32(ap[8 * HSTR]);
                u32t ua2 = f2tf32(ap[4]);
                u32t ua3 = f2tf32(ap[8 * HSTR + 4]);
                const uint2* bp = &S.Mp[(kt * 4 + tig) * MP_STR + gid];
                #pragma unroll
                for (int jt = 0; jt < 8; jt++) {
                    uint2 bb = bp[jt * 8];
                    mma_tf32(C1[jt][0], C1[jt][1], C1[jt][2], C1[jt][3],
                             ua0, ua1, ua2, ua3, bb.x, bb.y);
                }
            }
            #pragma unroll
            for (int jt = 0; jt < 8; jt++) {
                float cb0 = S.cbias[jt * 8 + 2 * tig], cb1 = S.cbias[jt * 8 + 2 * tig + 1];
                C1[jt][0] = fmaxf(C1[jt][0] + cb0, 0.f);
                C1[jt][1] = fmaxf(C1[jt][1] + cb1, 0.f);
                C1[jt][2] = fmaxf(C1[jt][2] + cb0, 0.f);
                C1[jt][3] = fmaxf(C1[jt][3] + cb1, 0.f);
            }

            float C2[4][4] = {};
            #pragma unroll
            for (int kt = 0; kt < 8; kt++) {
                float v00 = __shfl_sync(0xffffffffu, C1[kt][0], src0);
                float v01 = __shfl_sync(0xffffffffu, C1[kt][1], src0);
                float v10 = __shfl_sync(0xffffffffu, C1[kt][2], src0);
                float v11 = __shfl_sync(0xffffffffu, C1[kt][3], src0);
                float v20 = __shfl_sync(0xffffffffu, C1[kt][0], src2);
                float v21 = __shfl_sync(0xffffffffu, C1[kt][1], src2);
                float v30 = __shfl_sync(0xffffffffu, C1[kt][2], src2);
                float v31 = __shfl_sync(0xffffffffu, C1[kt][3], src2);
                u32t ua0 = f2tf32(odd ? v01 : v00);
                u32t ua1 = f2tf32(odd ? v11 : v10);
                u32t ua2 = f2tf32(odd ? v21 : v20);
                u32t ua3 = f2tf32(odd ? v31 : v30);
                const uint2* bp = &S.W1p[(kt * 4 + tig) * W1P_STR + gid];
                #pragma unroll
                for (int jt = 0; jt < 4; jt++) {
                    uint2 bb = bp[jt * 8];
                    mma_tf32(C2[jt][0], C2[jt][1], C2[jt][2], C2[jt][3],
                             ua0, ua1, ua2, ua3, bb.x, bb.y);
                }
            }
            float sr = 0.f, sr8 = 0.f;
            #pragma unroll
            for (int jt = 0; jt < 4; jt++) {
                int j = jt * 8 + 2 * tig;
                float b0v = S.ab1s[j], b1v = S.ab1s[j + 1];
                float w0v = S.aW2s[j], w1v = S.aW2s[j + 1];
                sr  += fmaxf(C2[jt][0] + b0v, 0.f) * w0v + fmaxf(C2[jt][1] + b1v, 0.f) * w1v;
                sr8 += fmaxf(C2[jt][2] + b0v, 0.f) * w0v + fmaxf(C2[jt][3] + b1v, 0.f) * w1v;
            }
            sr  += __shfl_xor_sync(0xffffffffu, sr, 1);
            sr  += __shfl_xor_sync(0xffffffffu, sr, 2);
            sr8 += __shfl_xor_sync(0xffffffffu, sr8, 1);
            sr8 += __shfl_xor_sync(0xffffffffu, sr8, 2);
            if (tig == 0) {
                S.scores[l0 + gid]     = sr + ab2v;
                S.scores[l0 + gid + 8] = sr8 + ab2v;
            }
        }
        __syncthreads();

        // ===== softmax by warp 0 only (1 barrier instead of 3) =====
        if (w == 0) {
            const int* hs = &history_seq[b * LSEQ];
            float vals[7];
            float mx = -3.402823466e38f;
            #pragma unroll
            for (int i = 0; i < 7; i++) {
                int l = lane + 32 * i;
                float sv = -3.402823466e38f;
                if (l < LSEQ) {
                    sv = S.scores[l];
                    if (hs[l] == 0) sv = -1.0e9f;
                }
                vals[i] = sv;
                mx = fmaxf(mx, sv);
            }
            #pragma unroll
            for (int o = 16; o; o >>= 1) mx = fmaxf(mx, __shfl_xor_sync(0xffffffffu, mx, o));
            float sum = 0.f;
            #pragma unroll
            for (int i = 0; i < 7; i++) {
                int l = lane + 32 * i;
                if (l < LSEQ) {
                    float e = expf(vals[i] - mx);
                    S.scores[l] = e;
                    sum += e;
                }
            }
            #pragma unroll
            for (int o = 16; o; o >>= 1) sum += __shfl_xor_sync(0xffffffffu, sum, o);
            if (lane == 0) S.red[14] = sum;
        }
        __syncthreads();

        // ===== pooling with unnormalized e =====
        {
            int kq = tid & 15, lg = tid >> 4;   // lg: 0..25
            int k4 = kq * 4;
            u64t a01 = 0ull, a23 = 0ull;
            for (int l = lg; l < LSEQ; l += 26) {
                u64t sd = dup2(S.scores[l]);
                ulonglong2 h = *(const ulonglong2*)&S.histL[l * HSTR + k4];
                fma2(a01, h.x, sd);
                fma2(a23, h.y, sd);
            }
            float p0, p1, p2, p3;
            unpack2(a01, p0, p1);
            unpack2(a23, p2, p3);
            S.poolbuf[lg * 64 + k4 + 0] = p0;
            S.poolbuf[lg * 64 + k4 + 1] = p1;
            S.poolbuf[lg * 64 + k4 + 2] = p2;
            S.poolbuf[lg * 64 + k4 + 3] = p3;
        }
        __syncthreads();
        if (tid < 64) {
            float p = 0.f;
            #pragma unroll
            for (int g = 0; g < 26; g++) p += S.poolbuf[g * 64 + tid];
            g_xbuf[b * 244 + 180 + tid] = p * (1.f / S.red[14]);
        }
        // ---- assemble x ----
        if (tid < 64) {
            g_xbuf[b * 244 + tid] = user_W[user_id[b] * 64 + tid];
        } else if (tid < 128) {
            g_xbuf[b * 244 + tid] = S.t[tid - 64];
        } else if (tid < 144) {
            g_xbuf[b * 244 + tid] = cat_W[item_category[b] * 16 + (tid - 128)];
        } else if (tid < 152) {
            g_xbuf[b * 244 + tid] = dur_W[item_dur_bkt[b] * 8 + (tid - 144)];
        } else if (tid < 177) {
            g_xbuf[b * 244 + tid] = user_dense[b * 25 + (tid - 152)];
        } else if (tid < 180) {
            g_xbuf[b * 244 + tid] = item_dense[b * 3 + (tid - 177)];
        }
        __syncthreads();   // protect histL/t/Mp/scores before next sample
    }
}

// ---- MLP: 16 samples/block, 512 threads (two 8-sample groups in parallel) ----
__global__ __launch_bounds__(512, 2) void mlp_kernel(
    const float* __restrict__ mW0, const float* __restrict__ mb0,
    const float* __restrict__ mW1, const float* __restrict__ mb1,
    const float* __restrict__ mW2, const float* __restrict__ mb2,
    float* __restrict__ out, int B)
{
    __shared__ __align__(16) float xsA[244 * 8];
    __shared__ __align__(16) float xsB[244 * 8];
    __shared__ __align__(16) float h0A[256 * 8];
    __shared__ __align__(16) float h0B[256 * 8];
    __shared__ __align__(16) float h1s[16 * 128];
    const int b0 = blockIdx.x * 16;
    const int tid = threadIdx.x;

    {
        int g = tid >> 8, r = tid & 255;      // g: 0/1, r: 0..255
        float* xs = g ? xsB : xsA;
        int base = b0 + g * 8;
        if (r < 244) {
            #pragma unroll
            for (int q = 0; q < 8; q++)
                if (base + q < B) xs[r * 8 + q] = g_xbuf[(base + q) * 244 + r];
        }
    }
    __syncthreads();

    // layer 0: 244 -> 256; group g handles 8 samples, col = tid&255
    {
        int g = tid >> 8, col = tid & 255;
        const float* xs = g ? xsB : xsA;
        float* h0 = g ? h0B : h0A;
        u64t acc[4];
        u64t bias = dup2(mb0[col]);
        #pragma unroll
        for (int p = 0; p < 4; p++) acc[p] = bias;
        #pragma unroll 1
        for (int i = 0; i < 240; i += 8) {
            float wv[8];
            #pragma unroll
            for (int u = 0; u < 8; u++) wv[u] = mW0[(i + u) * 256 + col];
            #pragma unroll
            for (int u = 0; u < 8; u++) {
                u64t wd = dup2(wv[u]);
                ulonglong2 a01 = *(const ulonglong2*)&xs[(i + u) * 8];
                ulonglong2 a23 = *(const ulonglong2*)&xs[(i + u) * 8 + 4];
                fma2(acc[0], a01.x, wd); fma2(acc[1], a01.y, wd);
                fma2(acc[2], a23.x, wd); fma2(acc[3], a23.y, wd);
            }
        }
        #pragma unroll
        for (int i = 240; i < 244; i++) {
            u64t wd = dup2(mW0[i * 256 + col]);
            ulonglong2 a01 = *(const ulonglong2*)&xs[i * 8];
            ulonglong2 a23 = *(const ulonglong2*)&xs[i * 8 + 4];
            fma2(acc[0], a01.x, wd); fma2(acc[1], a01.y, wd);
            fma2(acc[2], a23.x, wd); fma2(acc[3], a23.y, wd);
        }
        #pragma unroll
        for (int p = 0; p < 4; p++) {
            float a, c;
            unpack2(acc[p], a, c);
            h0[col * 8 + 2 * p]     = fmaxf(a, 0.f);
            h0[col * 8 + 2 * p + 1] = fmaxf(c, 0.f);
        }
    }
    __syncthreads();

    // layer 1: 256 -> 128; quarter q = tid>>7 handles 4 samples
    {
        int j = tid & 127, q = tid >> 7;     // q: 0..3
        int g = q >> 1, h = q & 1;
        const float* h0p = g ? h0B : h0A;
        u64t bias = dup2(mb1[j]);
        u64t acc[2] = {bias, bias};
        #pragma unroll 1
        for (int i = 0; i < 256; i += 8) {
            float wv[8];
            #pragma unroll
            for (int u = 0; u < 8; u++) wv[u] = mW1[(i + u) * 128 + j];
            #pragma unroll
            for (int u = 0; u < 8; u++) {
                u64t wd = dup2(wv[u]);
                ulonglong2 a01 = *(const ulonglong2*)&h0p[(i + u) * 8 + h * 4];
                fma2(acc[0], a01.x, wd); fma2(acc[1], a01.y, wd);
            }
        }
        int srow = g * 8 + h * 4;
        #pragma unroll
        for (int p = 0; p < 2; p++) {
            float a, c;
            unpack2(acc[p], a, c);
            h1s[(srow + 2 * p) * 128 + j]     = fmaxf(a, 0.f);
            h1s[(srow + 2 * p + 1) * 128 + j] = fmaxf(c, 0.f);
        }
    }
    __syncthreads();

    // layer 2: 128 -> 1, sigmoid; 16 warps, one sample each
    {
        int wsel = tid >> 5, lane = tid & 31;
        float m0 = mW2[lane], m1 = mW2[lane + 32], m2 = mW2[lane + 64], m3 = mW2[lane + 96];
        const float* hp = &h1s[wsel * 128];
        float v = hp[lane] * m0 + hp[lane + 32] * m1 + hp[lane + 64] * m2 + hp[lane + 96] * m3;
        #pragma unroll
        for (int o = 16; o; o >>= 1) v += __shfl_xor_sync(0xffffffffu, v, o);
        if (lane == 0 && (b0 + wsel) < B) {
            float logit = v + mb2[0];
            out[b0 + wsel] = 1.f / (1.f + expf(-logit));
        }
    }
}

extern "C" void kernel_launch(void* const* d_in, const int* in_sizes, int n_in,
                              void* d_out, int out_size)
{
    const int*   user_id       = (const int*)d_in[0];
    const int*   item_id       = (const int*)d_in[1];
    const int*   item_category = (const int*)d_in[2];
    const int*   item_dur_bkt  = (const int*)d_in[3];
    const float* user_dense    = (const float*)d_in[4];
    const float* item_dense    = (const float*)d_in[5];
    const int*   history_seq   = (const int*)d_in[6];
    const float* user_W        = (const float*)d_in[7];
    const float* item_W        = (const float*)d_in[8];
    const float* cat_W         = (const float*)d_in[9];
    const float* dur_W         = (const float*)d_in[10];
    const float* hist_W        = (const float*)d_in[11];
    const float* aW0 = (const float*)d_in[12];
    const float* ab0 = (const float*)d_in[13];
    const float* aW1 = (const float*)d_in[14];
    const float* ab1 = (const float*)d_in[15];
    const float* aW2 = (const float*)d_in[16];
    const float* ab2 = (const float*)d_in[17];
    const float* mW0 = (const float*)d_in[18];
    const float* mb0 = (const float*)d_in[19];
    const float* mW1 = (const float*)d_in[20];
    const float* mb1 = (const float*)d_in[21];
    const float* mW2 = (const float*)d_in[22];
    const float* mb2 = (const float*)d_in[23];

    const int B = in_sizes[0];
    float* out = (float*)d_out;

    precompute_kernel<<<16, 256>>>(aW0, aW1);

    cudaFuncSetAttribute(attn_kernel, cudaFuncAttributeMaxDynamicSharedMemorySize,
                         (int)sizeof(SmemA));

    attn_kernel<<<(B + SAMPLES - 1) / SAMPLES, NTHR, sizeof(SmemA)>>>(
        user_id, item_id, item_category, item_dur_bkt,
        user_dense, item_dense, history_seq,
        user_W, item_W, cat_W, dur_W, hist_W,
        aW0, ab0, ab1, aW2, ab2, B);

    mlp_kernel<<<(B + 15) / 16, 512>>>(mW0, mb0, mW1, mb1, mW2, mb2, out, B);
}

// round 16
// speedup vs baseline: 1.2160x; 1.0309x over previous
#include <cuda_runtime.h>
#include <math.h>

#define LSEQ 200
#define HSTR 68      // histL row stride (floats)
#define MP_STR 68    // Mp row stride (uint2)
#define W1P_STR 36   // W1p row stride (uint2)
#define NTHR 416     // 13 warps
#define SAMPLES 4
#define B_MAX 4096

__device__ float g_xbuf[B_MAX * 244];
__device__ __align__(16) unsigned int g_B3p[32 * 64 * 2];       // W_t - W_d packed tf32 pairs
__device__ __align__(16) unsigned int g_W1p[32 * W1P_STR * 2];  // aW1 packed tf32 pairs

typedef unsigned long long u64t;
typedef unsigned int u32t;

__device__ __forceinline__ u64t dup2(float x) {
    u64t r; asm("mov.b64 %0, {%1, %1};" : "=l"(r) : "f"(x)); return r;
}
__device__ __forceinline__ void fma2(u64t& d, u64t a, u64t b) {
    asm("fma.rn.f32x2 %0, %1, %2, %0;" : "+l"(d) : "l"(a), "l"(b));
}
__device__ __forceinline__ void unpack2(u64t v, float& a, float& b) {
    asm("mov.b64 {%0, %1}, %2;" : "=f"(a), "=f"(b) : "l"(v));
}
__device__ __forceinline__ u32t f2tf32(float f) {
    u32t u; asm("cvt.rna.tf32.f32 %0, %1;" : "=r"(u) : "f"(f)); return u;
}
__device__ __forceinline__ void mma_tf32(float& d0, float& d1, float& d2, float& d3,
                                         u32t a0, u32t a1, u32t a2, u32t a3,
                                         u32t b0, u32t b1) {
    asm volatile(
        "mma.sync.aligned.m16n8k8.row.col.f32.tf32.tf32.f32 "
        "{%0,%1,%2,%3},{%4,%5,%6,%7},{%8,%9},{%0,%1,%2,%3};"
        : "+f"(d0), "+f"(d1), "+f"(d2), "+f"(d3)
        : "r"(a0), "r"(a1), "r"(a2), "r"(a3), "r"(b0), "r"(b1));
}

// ---- precompute static tf32-packed weights ----
__global__ void precompute_kernel(const float* __restrict__ aW0,
                                  const float* __restrict__ aW1)
{
    int idx = blockIdx.x * blockDim.x + threadIdx.x;
    int stride = gridDim.x * blockDim.x;
    for (int p = idx; p < 4096; p += stride) {
        int k = p >> 6, j = p & 63;
        float b3 = aW0[(64 + k) * 64 + j] - aW0[(192 + k) * 64 + j];
        int kt = k >> 3, r = k & 7, tg = r & 3, half = r >> 2;
        g_B3p[(((kt * 4 + tg) * 64) + j) * 2 + half] = f2tf32(b3);
    }
    for (int p = idx; p < 2048; p += stride) {
        int k = p >> 5, j = p & 31;
        int kt = k >> 3, r = k & 7, tg = r & 3, half = r >> 2;
        g_W1p[(((kt * 4 + tg) * W1P_STR) + j) * 2 + half] = f2tf32(aW1[p]);
    }
}

struct __align__(16) SmemA {
    float histL[208 * HSTR];     // 56576 B
    uint2 Mp[32 * MP_STR];       // 17408 B (per-sample M, tf32 packed)
    uint2 W1p[32 * W1P_STR];     // 9216 B
    float ab0s[64];
    float cbias[64];
    float ab1s[32];
    float aW2s[32];
    float scores[208];
    float red[16];
    float poolbuf[26 * 64];      // 6656 B
};

// gather + Mp build + cbias for sample b; prefetch rows for sample bpre (if >= 0)
__device__ __forceinline__ void load_sample(
    SmemA& S, float* Mpf, int tid, int w, int gid, int tig,
    int b, int bpre,
    const int* __restrict__ history_seq, const float* __restrict__ hist_W,
    const float* __restrict__ item_W, const float* __restrict__ aW0,
    const int* __restrict__ item_id)
{
    const int iid = item_id[b];
    // fully-parallel gather
    {
        int c8 = tid & 7, lb = tid >> 3;   // lb: 0..51
        const int* hs = &history_seq[b * LSEQ];
        int r0 = hs[lb];
        int r1 = hs[lb + 52];
        int r2 = hs[lb + 104];
        bool has3 = (lb + 156) < LSEQ;
        int r3 = has3 ? hs[lb + 156] : 0;
        const float4* p0 = (const float4*)&hist_W[r0 * 64] + c8 * 2;
        const float4* p1 = (const float4*)&hist_W[r1 * 64] + c8 * 2;
        const float4* p2 = (const float4*)&hist_W[r2 * 64] + c8 * 2;
        const float4* p3 = (const float4*)&hist_W[r3 * 64] + c8 * 2;
        float4 a0 = p0[0], a1 = p0[1];
        float4 b0 = p1[0], b1 = p1[1];
        float4 c0 = p2[0], c1 = p2[1];
        float4 d0 = p3[0], d1 = p3[1];
        float* dst0 = &S.histL[lb * HSTR + c8 * 8];
        *(float4*)dst0 = a0; *(float4*)(dst0 + 4) = a1;
        float* dst1 = &S.histL[(lb + 52) * HSTR + c8 * 8];
        *(float4*)dst1 = b0; *(float4*)(dst1 + 4) = b1;
        float* dst2 = &S.histL[(lb + 104) * HSTR + c8 * 8];
        *(float4*)dst2 = c0; *(float4*)(dst2 + 4) = c1;
        if (has3) {
            float* dst3 = &S.histL[(lb + 156) * HSTR + c8 * 8];
            *(float4*)dst3 = d0; *(float4*)(dst3 + 4) = d1;
        }
    }
    // prefetch next sample's hist rows into L2
    if (bpre >= 0 && tid < LSEQ) {
        int rn = history_seq[bpre * LSEQ + tid];
        const char* pp = (const char*)&hist_W[rn * 64];
        asm volatile("prefetch.global.L2 [%0];" :: "l"(pp));
        asm volatile("prefetch.global.L2 [%0];" :: "l"(pp + 128));
    }
    // Mp build
    for (int g4 = tid; g4 < 1024; g4 += NTHR) {
        int k = g4 >> 4, j4 = (g4 & 15) << 2;
        float tk = __ldg(&item_W[iid * 64 + k]);
        float4 a0v  = *(const float4*)&aW0[k * 64 + j4];
        float4 a192 = *(const float4*)&aW0[(192 + k) * 64 + j4];
        float4 a128 = *(const float4*)&aW0[(128 + k) * 64 + j4];
        int kt = k >> 3, r = k & 7, tg = r & 3, half = r >> 2;
        float* dst = &Mpf[((kt * 4 + tg) * MP_STR) * 2 + half];
        dst[(j4 + 0) * 2] = __uint_as_float(f2tf32(a0v.x + a192.x + tk * a128.x));
        dst[(j4 + 1) * 2] = __uint_as_float(f2tf32(a0v.y + a192.y + tk * a128.y));
        dst[(j4 + 2) * 2] = __uint_as_float(f2tf32(a0v.z + a192.z + tk * a128.z));
        dst[(j4 + 3) * 2] = __uint_as_float(f2tf32(a0v.w + a192.w + tk * a128.w));
    }
    // cbias via MMA (warps 0..7)
    if (w < 8) {
        float d0 = 0.f, d1 = 0.f, d2 = 0.f, d3 = 0.f;
        #pragma unroll
        for (int kt = 0; kt < 8; kt++) {
            u32t ua0 = f2tf32(__ldg(&item_W[iid * 64 + kt * 8 + tig]));
            u32t ua2 = f2tf32(__ldg(&item_W[iid * 64 + kt * 8 + tig + 4]));
            uint2 bb = ((const uint2*)g_B3p)[(kt * 4 + tig) * 64 + w * 8 + gid];
            mma_tf32(d0, d1, d2, d3, ua0, ua0, ua2, ua2, bb.x, bb.y);
        }
        if (gid == 0) {
            S.cbias[w * 8 + 2 * tig]     = S.ab0s[w * 8 + 2 * tig] + d0;
            S.cbias[w * 8 + 2 * tig + 1] = S.ab0s[w * 8 + 2 * tig + 1] + d1;
        }
    }
}

__global__ __launch_bounds__(NTHR, 2) void attn_kernel(
    const int* __restrict__ user_id, const int* __restrict__ item_id,
    const int* __restrict__ item_category, const int* __restrict__ item_dur_bkt,
    const float* __restrict__ user_dense, const float* __restrict__ item_dense,
    const int* __restrict__ history_seq,
    const float* __restrict__ user_W, const float* __restrict__ item_W,
    const float* __restrict__ cat_W, const float* __restrict__ dur_W,
    const float* __restrict__ hist_W,
    const float* __restrict__ aW0, const float* __restrict__ ab0,
    const float* __restrict__ ab1, const float* __restrict__ aW2,
    const float* __restrict__ ab2, int B)
{
    extern __shared__ char smem_raw[];
    SmemA& S = *reinterpret_cast<SmemA*>(smem_raw);
    float* Mpf = (float*)S.Mp;
    const int tid = threadIdx.x;
    const int lane = tid & 31;
    const int w = tid >> 5;            // 0..12

    const int gid = lane >> 2;   // 0..7
    const int tig = lane & 3;    // 0..3
    const bool odd = tig & 1;
    const int src0 = gid * 4 + (tig >> 1);
    const int src2 = src0 + 2;
    const float ab2v = ab2[0];

    // ---- once-per-block staging ----
    for (int i = tid; i < 576; i += NTHR)
        ((uint4*)S.W1p)[i] = ((const uint4*)g_W1p)[i];
    if (tid < 64) S.ab0s[tid] = ab0[tid];
    else if (tid < 96) { S.aW2s[tid - 64] = aW2[tid - 64]; S.ab1s[tid - 64] = ab1[tid - 64]; }
    for (int p = tid; p < 8 * 64; p += NTHR)
        S.histL[(LSEQ + (p >> 6)) * HSTR + (p & 63)] = 0.f;
    __syncthreads();   // ab0s visible before load_sample's cbias

    // ---- prologue: load sample 0, prefetch sample 1 ----
    {
        int b0v = blockIdx.x * SAMPLES;
        if (b0v >= B) b0v = B - 1;
        int bp = blockIdx.x * SAMPLES + 1;
        load_sample(S, Mpf, tid, w, gid, tig, b0v, (bp < B && SAMPLES > 1) ? bp : -1,
                    history_seq, hist_W, item_W, aW0, item_id);
    }
    __syncthreads();

    for (int s = 0; s < SAMPLES; s++) {
        int b = blockIdx.x * SAMPLES + s;
        if (b >= B) b = B - 1;

        // ===== mainloop: warp w owns l-tile w =====
        {
            const int l0 = w * 16;

            float C1[8][4] = {};
            #pragma unroll
            for (int kt = 0; kt < 8; kt++) {
                const float* ap = &S.histL[(l0 + gid) * HSTR + kt * 8 + tig];
                u32t ua0 = f2tf32(ap[0]);
                u32t ua1 = f2tf32(ap[8 * HSTR]);
                u32t ua2 = f2tf32(ap[4]);
                u32t ua3 = f2tf32(ap[8 * HSTR + 4]);
                const uint2* bp = &S.Mp[(kt * 4 + tig) * MP_STR + gid];
                #pragma unroll
                for (int jt = 0; jt < 8; jt++) {
                    uint2 bb = bp[jt * 8];
                    mma_tf32(C1[jt][0], C1[jt][1], C1[jt][2], C1[jt][3],
                             ua0, ua1, ua2, ua3, bb.x, bb.y);
                }
            }
            #pragma unroll
            for (int jt = 0; jt < 8; jt++) {
                float cb0 = S.cbias[jt * 8 + 2 * tig], cb1 = S.cbias[jt * 8 + 2 * tig + 1];
                C1[jt][0] = fmaxf(C1[jt][0] + cb0, 0.f);
                C1[jt][1] = fmaxf(C1[jt][1] + cb1, 0.f);
                C1[jt][2] = fmaxf(C1[jt][2] + cb0, 0.f);
                C1[jt][3] = fmaxf(C1[jt][3] + cb1, 0.f);
            }

            float C2[4][4] = {};
            #pragma unroll
            for (int kt = 0; kt < 8; kt++) {
                float v00 = __shfl_sync(0xffffffffu, C1[kt][0], src0);
                float v01 = __shfl_sync(0xffffffffu, C1[kt][1], src0);
                float v10 = __shfl_sync(0xffffffffu, C1[kt][2], src0);
                float v11 = __shfl_sync(0xffffffffu, C1[kt][3], src0);
                float v20 = __shfl_sync(0xffffffffu, C1[kt][0], src2);
                float v21 = __shfl_sync(0xffffffffu, C1[kt][1], src2);
                float v30 = __shfl_sync(0xffffffffu, C1[kt][2], src2);
                float v31 = __shfl_sync(0xffffffffu, C1[kt][3], src2);
                u32t ua0 = f2tf32(odd ? v01 : v00);
                u32t ua1 = f2tf32(odd ? v11 : v10);
                u32t ua2 = f2tf32(odd ? v21 : v20);
                u32t ua3 = f2tf32(odd ? v31 : v30);
                const uint2* bp = &S.W1p[(kt * 4 + tig) * W1P_STR + gid];
                #pragma unroll
                for (int jt = 0; jt < 4; jt++) {
                    uint2 bb = bp[jt * 8];
                    mma_tf32(C2[jt][0], C2[jt][1], C2[jt][2], C2[jt][3],
                             ua0, ua1, ua2, ua3, bb.x, bb.y);
                }
            }
            float sr = 0.f, sr8 = 0.f;
            #pragma unroll
            for (int jt = 0; jt < 4; jt++) {
                int j = jt * 8 + 2 * tig;
                float b0v = S.ab1s[j], b1v = S.ab1s[j + 1];
                float w0v = S.aW2s[j], w1v = S.aW2s[j + 1];
                sr  += fmaxf(C2[jt][0] + b0v, 0.f) * w0v + fmaxf(C2[jt][1] + b1v, 0.f) * w1v;
                sr8 += fmaxf(C2[jt][2] + b0v, 0.f) * w0v + fmaxf(C2[jt][3] + b1v, 0.f) * w1v;
            }
            sr  += __shfl_xor_sync(0xffffffffu, sr, 1);
            sr  += __shfl_xor_sync(0xffffffffu, sr, 2);
            sr8 += __shfl_xor_sync(0xffffffffu, sr8, 1);
            sr8 += __shfl_xor_sync(0xffffffffu, sr8, 2);
            if (tig == 0) {
                S.scores[l0 + gid]     = sr + ab2v;
                S.scores[l0 + gid + 8] = sr8 + ab2v;
            }
        }
        __syncthreads();

        // ===== softmax by warp 0 only =====
        if (w == 0) {
            const int* hs = &history_seq[b * LSEQ];
            float vals[7];
            float mx = -3.402823466e38f;
            #pragma unroll
            for (int i = 0; i < 7; i++) {
                int l = lane + 32 * i;
                float sv = -3.402823466e38f;
                if (l < LSEQ) {
                    sv = S.scores[l];
                    if (hs[l] == 0) sv = -1.0e9f;
                }
                vals[i] = sv;
                mx = fmaxf(mx, sv);
            }
            #pragma unroll
            for (int o = 16; o; o >>= 1) mx = fmaxf(mx, __shfl_xor_sync(0xffffffffu, mx, o));
            float sum = 0.f;
            #pragma unroll
            for (int i = 0; i < 7; i++) {
                int l = lane + 32 * i;
                if (l < LSEQ) {
                    float e = expf(vals[i] - mx);
                    S.scores[l] = e;
                    sum += e;
                }
            }
            #pragma unroll
            for (int o = 16; o; o >>= 1) sum += __shfl_xor_sync(0xffffffffu, sum, o);
            if (lane == 0) S.red[14] = sum;
        }
        __syncthreads();

        // ===== pooling with unnormalized e (reads histL + scores) =====
        {
            int kq = tid & 15, lg = tid >> 4;   // lg: 0..25
            int k4 = kq * 4;
            u64t a01 = 0ull, a23 = 0ull;
            for (int l = lg; l < LSEQ; l += 26) {
                u64t sd = dup2(S.scores[l]);
                ulonglong2 h = *(const ulonglong2*)&S.histL[l * HSTR + k4];
                fma2(a01, h.x, sd);
                fma2(a23, h.y, sd);
            }
            float p0, p1, p2, p3;
            unpack2(a01, p0, p1);
            unpack2(a23, p2, p3);
            S.poolbuf[lg * 64 + k4 + 0] = p0;
            S.poolbuf[lg * 64 + k4 + 1] = p1;
            S.poolbuf[lg * 64 + k4 + 2] = p2;
            S.poolbuf[lg * 64 + k4 + 3] = p3;
        }
        __syncthreads();

        // ===== combined: reduce+assembly(s) || load_sample(s+1) =====
        if (tid < 64) {
            float p = 0.f;
            #pragma unroll
            for (int g = 0; g < 26; g++) p += S.poolbuf[g * 64 + tid];
            g_xbuf[b * 244 + 180 + tid] = p * (1.f / S.red[14]);
            g_xbuf[b * 244 + tid] = user_W[user_id[b] * 64 + tid];
        } else if (tid < 128) {
            g_xbuf[b * 244 + tid] = item_W[item_id[b] * 64 + (tid - 64)];
        } else if (tid < 144) {
            g_xbuf[b * 244 + tid] = cat_W[item_category[b] * 16 + (tid - 128)];
        } else if (tid < 152) {
            g_xbuf[b * 244 + tid] = dur_W[item_dur_bkt[b] * 8 + (tid - 144)];
        } else if (tid < 177) {
            g_xbuf[b * 244 + tid] = user_dense[b * 25 + (tid - 152)];
        } else if (tid < 180) {
            g_xbuf[b * 244 + tid] = item_dense[b * 3 + (tid - 177)];
        }
        if (s + 1 < SAMPLES) {
            int bn = blockIdx.x * SAMPLES + s + 1;
            if (bn >= B) bn = B - 1;
            int bp = blockIdx.x * SAMPLES + s + 2;
            load_sample(S, Mpf, tid, w, gid, tig, bn,
                        (s + 2 < SAMPLES && bp < B) ? bp : -1,
                        history_seq, hist_W, item_W, aW0, item_id);
        }
        __syncthreads();
    }
}

// ---- MLP: 16 samples/block, 512 threads (two 8-sample groups in parallel) ----
__global__ __launch_bounds__(512, 2) void mlp_kernel(
    const float* __restrict__ mW0, const float* __restrict__ mb0,
    const float* __restrict__ mW1, const float* __restrict__ mb1,
    const float* __restrict__ mW2, const float* __restrict__ mb2,
    float* __restrict__ out, int B)
{
    __shared__ __align__(16) float xsA[244 * 8];
    __shared__ __align__(16) float xsB[244 * 8];
    __shared__ __align__(16) float h0A[256 * 8];
    __shared__ __align__(16) float h0B[256 * 8];
    __shared__ __align__(16) float h1s[16 * 128];
    const int b0 = blockIdx.x * 16;
    const int tid = threadIdx.x;

    {
        int g = tid >> 8, r = tid & 255;      // g: 0/1, r: 0..255
        float* xs = g ? xsB : xsA;
        int base = b0 + g * 8;
        if (r < 244) {
            #pragma unroll
            for (int q = 0; q < 8; q++)
                if (base + q < B) xs[r * 8 + q] = g_xbuf[(base + q) * 244 + r];
        }
    }
    __syncthreads();

    // layer 0: 244 -> 256; group g handles 8 samples, col = tid&255
    {
        int g = tid >> 8, col = tid & 255;
        const float* xs = g ? xsB : xsA;
        float* h0 = g ? h0B : h0A;
        u64t acc[4];
        u64t bias = dup2(mb0[col]);
        #pragma unroll
        for (int p = 0; p < 4; p++) acc[p] = bias;
        #pragma unroll 1
        for (int i = 0; i < 240; i += 8) {
            float wv[8];
            #pragma unroll
            for (int u = 0; u < 8; u++) wv[u] = mW0[(i + u) * 256 + col];
            #pragma unroll
            for (int u = 0; u < 8; u++) {
                u64t wd = dup2(wv[u]);
                ulonglong2 a01 = *(const ulonglong2*)&xs[(i + u) * 8];
                ulonglong2 a23 = *(const ulonglong2*)&xs[(i + u) * 8 + 4];
                fma2(acc[0], a01.x, wd); fma2(acc[1], a01.y, wd);
                fma2(acc[2], a23.x, wd); fma2(acc[3], a23.y, wd);
            }
        }
        #pragma unroll
        for (int i = 240; i < 244; i++) {
            u64t wd = dup2(mW0[i * 256 + col]);
            ulonglong2 a01 = *(const ulonglong2*)&xs[i * 8];
            ulonglong2 a23 = *(const ulonglong2*)&xs[i * 8 + 4];
            fma2(acc[0], a01.x, wd); fma2(acc[1], a01.y, wd);
            fma2(acc[2], a23.x, wd); fma2(acc[3], a23.y, wd);
        }
        #pragma unroll
        for (int p = 0; p < 4; p++) {
            float a, c;
            unpack2(acc[p], a, c);
            h0[col * 8 + 2 * p]     = fmaxf(a, 0.f);
            h0[col * 8 + 2 * p + 1] = fmaxf(c, 0.f);
        }
    }
    __syncthreads();

    // layer 1: 256 -> 128; quarter q = tid>>7 handles 4 samples
    {
        int j = tid & 127, q = tid >> 7;     // q: 0..3
        int g = q >> 1, h = q & 1;
        const float* h0p = g ? h0B : h0A;
        u64t bias = dup2(mb1[j]);
        u64t acc[2] = {bias, bias};
        #pragma unroll 1
        for (int i = 0; i < 256; i += 8) {
            float wv[8];
            #pragma unroll
            for (int u = 0; u < 8; u++) wv[u] = mW1[(i + u) * 128 + j];
            #pragma unroll
            for (int u = 0; u < 8; u++) {
                u64t wd = dup2(wv[u]);
                ulonglong2 a01 = *(const ulonglong2*)&h0p[(i + u) * 8 + h * 4];
                fma2(acc[0], a01.x, wd); fma2(acc[1], a01.y, wd);
            }
        }
        int srow = g * 8 + h * 4;
        #pragma unroll
        for (int p = 0; p < 2; p++) {
            float a, c;
            unpack2(acc[p], a, c);
            h1s[(srow + 2 * p) * 128 + j]     = fmaxf(a, 0.f);
            h1s[(srow + 2 * p + 1) * 128 + j] = fmaxf(c, 0.f);
        }
    }
    __syncthreads();

    // layer 2: 128 -> 1, sigmoid; 16 warps, one sample each
    {
        int wsel = tid >> 5, lane = tid & 31;
        float m0 = mW2[lane], m1 = mW2[lane + 32], m2 = mW2[lane + 64], m3 = mW2[lane + 96];
        const float* hp = &h1s[wsel * 128];
        float v = hp[lane] * m0 + hp[lane + 32] * m1 + hp[lane + 64] * m2 + hp[lane + 96] * m3;
        #pragma unroll
        for (int o = 16; o; o >>= 1) v += __shfl_xor_sync(0xffffffffu, v, o);
        if (lane == 0 && (b0 + wsel) < B) {
            float logit = v + mb2[0];
            out[b0 + wsel] = 1.f / (1.f + expf(-logit));
        }
    }
}

extern "C" void kernel_launch(void* const* d_in, const int* in_sizes, int n_in,
                              void* d_out, int out_size)
{
    const int*   user_id       = (const int*)d_in[0];
    const int*   item_id       = (const int*)d_in[1];
    const int*   item_category = (const int*)d_in[2];
    const int*   item_dur_bkt  = (const int*)d_in[3];
    const float* user_dense    = (const float*)d_in[4];
    const float* item_dense    = (const float*)d_in[5];
    const int*   history_seq   = (const int*)d_in[6];
    const float* user_W        = (const float*)d_in[7];
    const float* item_W        = (const float*)d_in[8];
    const float* cat_W         = (const float*)d_in[9];
    const float* dur_W         = (const float*)d_in[10];
    const float* hist_W        = (const float*)d_in[11];
    const float* aW0 = (const float*)d_in[12];
    const float* ab0 = (const float*)d_in[13];
    const float* aW1 = (const float*)d_in[14];
    const float* ab1 = (const float*)d_in[15];
    const float* aW2 = (const float*)d_in[16];
    const float* ab2 = (const float*)d_in[17];
    const float* mW0 = (const float*)d_in[18];
    const float* mb0 = (const float*)d_in[19];
    const float* mW1 = (const float*)d_in[20];
    const float* mb1 = (const float*)d_in[21];
    const float* mW2 = (const float*)d_in[22];
    const float* mb2 = (const float*)d_in[23];

    const int B = in_sizes[0];
    float* out = (float*)d_out;

    precompute_kernel<<<16, 256>>>(aW0, aW1);

    cudaFuncSetAttribute(attn_kernel, cudaFuncAttributeMaxDynamicSharedMemorySize,
                         (int)sizeof(SmemA));

    attn_kernel<<<(B + SAMPLES - 1) / SAMPLES, NTHR, sizeof(SmemA)>>>(
        user_id, item_id, item_category, item_dur_bkt,
        user_dense, item_dense, history_seq,
        user_W, item_W, cat_W, dur_W, hist_W,
        aW0, ab0, ab1, aW2, ab2, B);

    mlp_kernel<<<(B + 15) / 16, 512>>>(mW0, mb0, mW1, mb1, mW2, mb2, out, B);
}